// round 10
// baseline (speedup 1.0000x reference)
#include <cuda_runtime.h>
#include <cuda_bf16.h>
#include <math.h>

#define SS 512
#define BB 128
#define EE 128
#define HH 128
#define KK 32
#define TAG_START 30
#define TAG_END 31

// ----------------------------- device scratch ------------------------------
__device__ float g_xW[(size_t)SS * BB * 1024];   // [s*B+b][d*512 + g*128 + u]
__device__ float g_hs[2][(size_t)SS * BB * HH];  // per-dir h at original time
__device__ float g_feats[(size_t)BB * SS * KK];  // [b][s][k]
__device__ float g_num[BB];
__device__ float g_den[BB];

// ----------------------------- helpers -------------------------------------
__device__ __forceinline__ void fma2(unsigned long long& d, unsigned long long a,
                                     unsigned long long b) {
  asm("fma.rn.f32x2 %0, %1, %2, %0;" : "+l"(d) : "l"(a), "l"(b));
}
__device__ __forceinline__ unsigned long long pack2(float x, float y) {
  unsigned long long r;
  asm("mov.b64 %0, {%1, %2};" : "=l"(r) : "f"(x), "f"(y));
  return r;
}
__device__ __forceinline__ float plo(unsigned long long v) {
  return __uint_as_float((unsigned)v);
}
__device__ __forceinline__ float phi(unsigned long long v) {
  return __uint_as_float((unsigned)(v >> 32));
}
__device__ __forceinline__ float sigm(float x) {
  return __fdividef(1.f, 1.f + __expf(-x));
}
__device__ __forceinline__ float ftanh(float x) {
  float e = __expf(-2.f * fmaxf(x, -20.f));
  return __fdividef(1.f - e, 1.f + e);
}

#define CLUSTER_SYNC()                                              \
  do {                                                              \
    asm volatile("barrier.cluster.arrive.aligned;" ::: "memory");   \
    asm volatile("barrier.cluster.wait.aligned;" ::: "memory");     \
  } while (0)

// ------------------- profiling-window shim (no-op kernel) ------------------
__global__ void dummy_k() {}

// ------------- 1) fused embedding + input GEMM: xW = X @ Wih^T + b ---------
__global__ void __launch_bounds__(256) gemm_xw_k(
    const int* __restrict__ sentence, const float* __restrict__ table,
    const float* __restrict__ Wf, const float* __restrict__ Wb,
    const float* __restrict__ bihf, const float* __restrict__ bhhf,
    const float* __restrict__ bihb, const float* __restrict__ bhhb) {
  __shared__ __align__(16) unsigned long long As2[32 * 128];  // [k][m] dup
  __shared__ __align__(16) float Bs[32 * 68];                 // [k][n] padded
  int tid = threadIdx.x;
  int bm = blockIdx.x, bn = blockIdx.y;
  int r0 = bm * 128, n0 = bn * 64;
  int tx = tid & 15, ty = tid >> 4;

  int arow = tid >> 1, akh = (tid & 1) * 16;
  int r = r0 + arow;
  int s = r >> 7, b = r & 127;
  const float* asrc = table + (size_t)sentence[b * SS + s] * EE;
  int brow = tid >> 2, bkq = (tid & 3) * 8;
  int jg = n0 + brow;
  const float* wsrc = (jg < 512) ? Wf + (size_t)jg * EE
                                 : Wb + (size_t)(jg - 512) * EE;

  unsigned long long acc2[8][2];
#pragma unroll
  for (int i = 0; i < 8; i++) { acc2[i][0] = 0ull; acc2[i][1] = 0ull; }

  for (int kt = 0; kt < 4; kt++) {
    int kb = kt * 32;
#pragma unroll
    for (int q = 0; q < 4; q++) {
      float4 v = *(const float4*)(asrc + kb + akh + q * 4);
      As2[(akh + q * 4 + 0) * 128 + arow] = pack2(v.x, v.x);
      As2[(akh + q * 4 + 1) * 128 + arow] = pack2(v.y, v.y);
      As2[(akh + q * 4 + 2) * 128 + arow] = pack2(v.z, v.z);
      As2[(akh + q * 4 + 3) * 128 + arow] = pack2(v.w, v.w);
    }
#pragma unroll
    for (int q = 0; q < 2; q++) {
      float4 v = *(const float4*)(wsrc + kb + bkq + q * 4);
      Bs[(bkq + q * 4 + 0) * 68 + brow] = v.x;
      Bs[(bkq + q * 4 + 1) * 68 + brow] = v.y;
      Bs[(bkq + q * 4 + 2) * 68 + brow] = v.z;
      Bs[(bkq + q * 4 + 3) * 68 + brow] = v.w;
    }
    __syncthreads();
#pragma unroll
    for (int kk = 0; kk < 32; kk++) {
      ulonglong2 a01 = *(const ulonglong2*)&As2[kk * 128 + ty * 8 + 0];
      ulonglong2 a23 = *(const ulonglong2*)&As2[kk * 128 + ty * 8 + 2];
      ulonglong2 a45 = *(const ulonglong2*)&As2[kk * 128 + ty * 8 + 4];
      ulonglong2 a67 = *(const ulonglong2*)&As2[kk * 128 + ty * 8 + 6];
      ulonglong2 bp = *(const ulonglong2*)&Bs[kk * 68 + tx * 4];
      fma2(acc2[0][0], a01.x, bp.x); fma2(acc2[0][1], a01.x, bp.y);
      fma2(acc2[1][0], a01.y, bp.x); fma2(acc2[1][1], a01.y, bp.y);
      fma2(acc2[2][0], a23.x, bp.x); fma2(acc2[2][1], a23.x, bp.y);
      fma2(acc2[3][0], a23.y, bp.x); fma2(acc2[3][1], a23.y, bp.y);
      fma2(acc2[4][0], a45.x, bp.x); fma2(acc2[4][1], a45.x, bp.y);
      fma2(acc2[5][0], a45.y, bp.x); fma2(acc2[5][1], a45.y, bp.y);
      fma2(acc2[6][0], a67.x, bp.x); fma2(acc2[6][1], a67.x, bp.y);
      fma2(acc2[7][0], a67.y, bp.x); fma2(acc2[7][1], a67.y, bp.y);
    }
    __syncthreads();
  }
  float bias[4];
#pragma unroll
  for (int jj = 0; jj < 4; jj++) {
    int j = n0 + tx * 4 + jj;
    bias[jj] = (j < 512) ? (bihf[j] + bhhf[j]) : (bihb[j - 512] + bhhb[j - 512]);
  }
  int n = n0 + tx * 4;
#pragma unroll
  for (int ii = 0; ii < 8; ii++) {
    int m = r0 + ty * 8 + ii;
    float4 o;
    o.x = plo(acc2[ii][0]) + bias[0];
    o.y = phi(acc2[ii][0]) + bias[1];
    o.z = plo(acc2[ii][1]) + bias[2];
    o.w = phi(acc2[ii][1]) + bias[3];
    *(float4*)&g_xW[(size_t)m * 1024 + n] = o;
  }
}

// --------------- 2) bidirectional LSTM recurrence (cluster pairs) ----------
// 64 clusters of 2 CTAs; cluster = (dir, 4-batch tile); CTA = u-half.
// 512 threads / 16 warps per CTA: warp = (u-octet, gate-half gh). Each
// thread holds 2 gates x 32 k of W_hh in registers (64 floats) -> ~115 regs,
// 4 warps/SMSP to hide LDS/SHFL/LDG/barrier latency (R9 profile: 2 warps/SMSP
// could not; 2300 stall cyc/step on a 1024-cyc FFMA2 floor).
// Gate halves recombine via a 2KB smem buffer + one __syncthreads; each half
// owns 2 batches' activations. h exchange: DSMEM store + 32-arrival
// phase-parity mbarrier per step.
__global__ void __cluster_dims__(2, 1, 1) __launch_bounds__(512, 1) lstm_k(
    const float* __restrict__ Whhf, const float* __restrict__ Whhb,
    const float* __restrict__ h0, const float* __restrict__ c0) {
  __shared__ __align__(16) float hb[2][4 * 132];   // [parity][b*132 + u]
  __shared__ __align__(16) float gbuf[4 * 132];    // [b*132 + ul*2 + {0,1}]
  __shared__ __align__(8) unsigned long long bar;
  int rank = blockIdx.x & 1;
  int cl = blockIdx.x >> 1;
  int d = cl >> 5;
  int b0 = (cl & 31) * 4;
  int tid = threadIdx.x;
  int lane = tid & 31;
  int w = tid >> 5;          // 0..15
  int uoct = w >> 1;         // 0..7
  int gh = w & 1;            // gate half: this thread's gates {2gh, 2gh+1}
  int ks = lane >> 3;        // k-slice 0..3 (32 k each)
  int rr = lane & 7;
  int ul = uoct * 8 + rr;    // 0..63
  int u = rank * 64 + ul;

  const float* Whh = d ? Whhb : Whhf;
  // register-resident weights: 2 gates x 32 k
  unsigned long long w2[2][16];
#pragma unroll
  for (int gi = 0; gi < 2; gi++) {
    const float* wr = Whh + (size_t)((gh * 2 + gi) * 128 + u) * 128 + ks * 32;
#pragma unroll
    for (int q = 0; q < 8; q++) {
      ulonglong2 v = *(const ulonglong2*)(wr + q * 4);
      w2[gi][q * 2] = v.x;
      w2[gi][q * 2 + 1] = v.y;
    }
  }
  // init h (4 batches, full 128 u)
  for (int i = tid; i < 512; i += 512) {
    int j = i >> 7, uu = i & 127;
    hb[0][j * 132 + uu] = h0[(d * BB + b0 + j) * HH + uu];
  }
  // ownership: gh=0 owns batches {0,1}, gh=1 owns {2,3}; owner lanes ks<2.
  bool is_owner = (ks < 2);
  int ob = gh * 2 + ks;  // owned batch (valid when is_owner)
  float c = 0.f;
  if (is_owner) c = c0[(d * BB + b0 + ob) * HH + u];

  unsigned hb_u32, bar_u32;
  asm("{ .reg .u64 t; cvta.to.shared.u64 t, %1; cvt.u32.u64 %0, t; }"
      : "=r"(hb_u32) : "l"(&hb[0][0]));
  asm("{ .reg .u64 t; cvta.to.shared.u64 t, %1; cvt.u32.u64 %0, t; }"
      : "=r"(bar_u32) : "l"(&bar));
  unsigned peer_base, peer_bar;
  asm("mapa.shared::cluster.u32 %0, %1, %2;"
      : "=r"(peer_base) : "r"(hb_u32), "r"(rank ^ 1));
  asm("mapa.shared::cluster.u32 %0, %1, %2;"
      : "=r"(peer_bar) : "r"(bar_u32), "r"(rank ^ 1));

  if (tid == 0) {
    asm volatile("mbarrier.init.shared.b64 [%0], 32;" :: "r"(bar_u32)
                 : "memory");
  }
  __syncthreads();
  CLUSTER_SYNC();  // mbarrier init + hb[0] visible cluster-wide

  for (int t = 0; t < SS; t++) {
    const float* cur = hb[t & 1];
    int np = (t + 1) & 1;
    int tx = d ? (SS - 1 - t) : t;
    // owners prefetch their batch's 4 xW gate values
    float xw0 = 0.f, xw1 = 0.f, xw2 = 0.f, xw3 = 0.f;
    if (is_owner) {
      const float* xwb =
          g_xW + ((size_t)tx * BB + b0 + ob) * 1024 + d * 512 + u;
      xw0 = __ldcg(xwb);
      xw1 = __ldcg(xwb + 128);
      xw2 = __ldcg(xwb + 256);
      xw3 = __ldcg(xwb + 384);
    }

    // matvec: 4 batches x 2 gates x 32 k per thread
    unsigned long long acc2[4][2];
#pragma unroll
    for (int j = 0; j < 4; j++) { acc2[j][0] = 0ull; acc2[j][1] = 0ull; }
#pragma unroll
    for (int q = 0; q < 8; q++) {
      int k = ks * 32 + q * 4;
      ulonglong2 hv[4];
#pragma unroll
      for (int j = 0; j < 4; j++)
        hv[j] = *(const ulonglong2*)&cur[j * 132 + k];
#pragma unroll
      for (int j = 0; j < 4; j++) {
#pragma unroll
        for (int gi = 0; gi < 2; gi++) {
          fma2(acc2[j][gi], hv[j].x, w2[gi][q * 2]);
          fma2(acc2[j][gi], hv[j].y, w2[gi][q * 2 + 1]);
        }
      }
    }
    // reduce over the 4 k-slices (all lanes end with full sums)
    float accf[4][2];
#pragma unroll
    for (int j = 0; j < 4; j++)
#pragma unroll
      for (int gi = 0; gi < 2; gi++) {
        float v = plo(acc2[j][gi]) + phi(acc2[j][gi]);
        v += __shfl_xor_sync(0xffffffffu, v, 8);
        v += __shfl_xor_sync(0xffffffffu, v, 16);
        accf[j][gi] = v;
      }
    // cross-half gate exchange: store my 2 gates for the OTHER half's batches
    bool is_writer = gh ? (ks < 2) : (ks >= 2);
    if (is_writer) {
      *(float2*)&gbuf[ks * 132 + ul * 2] = make_float2(accf[ks][0], accf[ks][1]);
    }
    __syncthreads();

    if (is_owner) {
      float2 og = *(const float2*)&gbuf[ob * 132 + ul * 2];
      float gi_, gf, gg, go;
      if (gh == 0) {  // own = {i,f}, other = {g,o}
        gi_ = accf[ob][0] + xw0;
        gf  = accf[ob][1] + xw1;
        gg  = og.x + xw2;
        go  = og.y + xw3;
      } else {        // own = {g,o}, other = {i,f}
        gi_ = og.x + xw0;
        gf  = og.y + xw1;
        gg  = accf[ob][0] + xw2;
        go  = accf[ob][1] + xw3;
      }
      float si = sigm(gi_), sf = sigm(gf), tg = ftanh(gg), so = sigm(go);
      c = sf * c + si * tg;
      float h = so * ftanh(c);
      hb[np][ob * 132 + u] = h;
      unsigned pa = peer_base + (unsigned)(np * 528 + ob * 132 + u) * 4u;
      asm volatile("st.shared::cluster.f32 [%0], %1;" :: "r"(pa), "f"(h));
      g_hs[d][((size_t)tx * BB + b0 + ob) * HH + u] = h;
    }

    __syncwarp();
    if (lane == 0) {
      asm volatile("mbarrier.arrive.release.cta.shared::cta.b64 _, [%0];"
                   :: "r"(bar_u32) : "memory");
      asm volatile(
          "mbarrier.arrive.release.cluster.shared::cluster.b64 _, [%0];"
          :: "r"(peer_bar) : "memory");
    }
    {
      unsigned parity = (unsigned)(t & 1);
      asm volatile(
          "{\n\t"
          ".reg .pred P;\n\t"
          "WL_%=:\n\t"
          "mbarrier.try_wait.parity.acquire.cluster.shared::cta.b64 P, [%0], %1, 0x989680;\n\t"
          "@P bra.uni WD_%=;\n\t"
          "bra.uni WL_%=;\n\t"
          "WD_%=:\n\t"
          "}"
          :: "r"(bar_u32), "r"(parity) : "memory");
    }
  }
  // keep both CTAs resident until all DSMEM traffic has completed
  CLUSTER_SYNC();
}

// -------------- 3) feats = concat(hf,hb) @ Wout^T + bout -------------------
__global__ void __launch_bounds__(256) feats_k(const float* __restrict__ Wout,
                                               const float* __restrict__ bout) {
  __shared__ __align__(16) float Wsh[32 * 260];
  __shared__ float bsh[32];
  int s = blockIdx.x;
  int tid = threadIdx.x;
  for (int i = tid; i < 2048; i += 256) {
    int k = i >> 6, m4 = i & 63;
    float4 v = ((const float4*)Wout)[i];
    *(float4*)&Wsh[k * 260 + m4 * 4] = v;
  }
  if (tid < 32) bsh[tid] = bout[tid];
  __syncthreads();
  int k = tid & 31, b0 = tid >> 5;
  for (int bb = 0; bb < 16; bb++) {
    int b = b0 + bb * 8;
    const float4* hf = (const float4*)&g_hs[0][((size_t)s * BB + b) * HH];
    const float4* hb2 = (const float4*)&g_hs[1][((size_t)s * BB + b) * HH];
    float acc = bsh[k];
#pragma unroll 8
    for (int m4 = 0; m4 < 32; m4++) {
      float4 hv = hf[m4];
      float4 wv = *(const float4*)&Wsh[k * 260 + m4 * 4];
      acc += hv.x * wv.x + hv.y * wv.y + hv.z * wv.z + hv.w * wv.w;
    }
#pragma unroll 8
    for (int m4 = 0; m4 < 32; m4++) {
      float4 hv = hb2[m4];
      float4 wv = *(const float4*)&Wsh[k * 260 + 128 + m4 * 4];
      acc += hv.x * wv.x + hv.y * wv.y + hv.z * wv.z + hv.w * wv.w;
    }
    g_feats[((size_t)b * SS + s) * KK + k] = acc;
  }
}

// ----------------------------- 4) CRF numerator ----------------------------
__global__ void __launch_bounds__(128) numer_k(const int* __restrict__ tags,
                                               const float* __restrict__ T) {
  __shared__ float red[128];
  int b = blockIdx.x;
  int tid = threadIdx.x;
  float sum = 0.f;
  for (int s = tid; s < SS; s += 128) {
    int cur = tags[b * SS + s];
    int prev = (s == 0) ? TAG_START : tags[b * SS + s - 1];
    sum += T[prev * KK + cur] + g_feats[((size_t)b * SS + s) * KK + cur];
  }
  red[tid] = sum;
  __syncthreads();
  for (int off = 64; off > 0; off >>= 1) {
    if (tid < off) red[tid] += red[tid + off];
    __syncthreads();
  }
  if (tid == 0) g_num[b] = red[0] + T[tags[b * SS + SS - 1] * KK + TAG_END];
}

// ---------------------------- 5) CRF denominator ---------------------------
__global__ void __launch_bounds__(256) denom_k(const float* __restrict__ T) {
  __shared__ float Tsh[32 * 33];
  int tid = threadIdx.x;
  int lane = tid & 31;
  int warp = tid >> 5;
  int b = blockIdx.x * 8 + warp;
  for (int i = tid; i < 1024; i += 256) Tsh[(i >> 5) * 33 + (i & 31)] = T[i];
  __syncthreads();

  float alpha = (lane == TAG_START) ? 0.f : -10000.f;
  const float* Trow = &Tsh[lane * 33];

  {
    float feat = g_feats[(size_t)b * SS * KK + lane];
    float tmp[32];
    float m = -3.0e38f;
#pragma unroll
    for (int p = 0; p < 32; p++) {
      float ap = __shfl_sync(0xffffffffu, alpha, p);
      tmp[p] = ap + Trow[p];
      m = fmaxf(m, tmp[p]);
    }
    float sum = 0.f;
#pragma unroll
    for (int p = 0; p < 32; p++) sum += __expf(tmp[p] - m);
    alpha = __logf(sum) + m + feat;
  }

  float rT[32];
#pragma unroll
  for (int p = 0; p < 32; p++) rT[p] = __expf(Trow[p]);

  for (int s = 1; s < SS; s++) {
    float feat = g_feats[((size_t)b * SS + s) * KK + lane];
    float m = alpha;
#pragma unroll
    for (int o = 16; o > 0; o >>= 1)
      m = fmaxf(m, __shfl_xor_sync(0xffffffffu, m, o));
    float E = __expf(alpha - m);
    float sum = 0.f;
#pragma unroll
    for (int p = 0; p < 32; p++)
      sum += __shfl_sync(0xffffffffu, E, p) * rT[p];
    alpha = __logf(sum) + m + feat;
  }
  float v = alpha + Tsh[lane * 33 + TAG_END];
  float m2 = v;
#pragma unroll
  for (int o = 16; o > 0; o >>= 1)
    m2 = fmaxf(m2, __shfl_xor_sync(0xffffffffu, m2, o));
  float s2 = __expf(v - m2);
#pragma unroll
  for (int o = 16; o > 0; o >>= 1) s2 += __shfl_xor_sync(0xffffffffu, s2, o);
  if (lane == 0) g_den[b] = __logf(s2) + m2;
}

// --------------------------------- 6) mean ---------------------------------
__global__ void __launch_bounds__(128) mean_k(float* __restrict__ out) {
  __shared__ float red[128];
  int tid = threadIdx.x;
  red[tid] = g_num[tid] - g_den[tid];
  __syncthreads();
  for (int off = 64; off > 0; off >>= 1) {
    if (tid < off) red[tid] += red[tid + off];
    __syncthreads();
  }
  if (tid == 0) out[0] = red[0] / 128.0f;
}

// ------------------------------- launcher ----------------------------------
extern "C" void kernel_launch(void* const* d_in, const int* in_sizes, int n_in,
                              void* d_out, int out_size) {
  const int*   sentence = (const int*)d_in[0];
  const int*   tags     = (const int*)d_in[1];
  const float* table    = (const float*)d_in[2];
  const float* W_ih_f   = (const float*)d_in[3];
  const float* W_hh_f   = (const float*)d_in[4];
  const float* b_ih_f   = (const float*)d_in[5];
  const float* b_hh_f   = (const float*)d_in[6];
  const float* W_ih_b   = (const float*)d_in[7];
  const float* W_hh_b   = (const float*)d_in[8];
  const float* b_ih_b   = (const float*)d_in[9];
  const float* b_hh_b   = (const float*)d_in[10];
  const float* W_out    = (const float*)d_in[11];
  const float* b_out    = (const float*)d_in[12];
  const float* trans    = (const float*)d_in[13];
  const float* h0       = (const float*)d_in[14];
  const float* c0       = (const float*)d_in[15];
  float* out = (float*)d_out;

  gemm_xw_k<<<dim3(512, 16), 256>>>(sentence, table, W_ih_f, W_ih_b,
                                    b_ih_f, b_hh_f, b_ih_b, b_hh_b);
  // keep the fixed ncu capture window on lstm_k (4th launch)
  dummy_k<<<1, 32>>>();
  dummy_k<<<1, 32>>>();
  lstm_k<<<128, 512>>>(W_hh_f, W_hh_b, h0, c0);
  feats_k<<<512, 256>>>(W_out, b_out);
  numer_k<<<128, 128>>>(tags, trans);
  denom_k<<<16, 256>>>(trans);
  mean_k<<<1, 128>>>(out);
}

// round 11
// speedup vs baseline: 1.1026x; 1.1026x over previous
#include <cuda_runtime.h>
#include <cuda_bf16.h>
#include <math.h>

#define SS 512
#define BB 128
#define EE 128
#define HH 128
#define KK 32
#define TAG_START 30
#define TAG_END 31

// ----------------------------- device scratch ------------------------------
__device__ float g_xW[(size_t)SS * BB * 1024];   // [s*B+b][d*512 + g*128 + u]
__device__ float g_hs[2][(size_t)SS * BB * HH];  // per-dir h at original time
__device__ float g_feats[(size_t)BB * SS * KK];  // [b][s][k]
__device__ float g_num[BB];
__device__ float g_den[BB];

// ----------------------------- helpers -------------------------------------
__device__ __forceinline__ void fma2(unsigned long long& d, unsigned long long a,
                                     unsigned long long b) {
  asm("fma.rn.f32x2 %0, %1, %2, %0;" : "+l"(d) : "l"(a), "l"(b));
}
__device__ __forceinline__ unsigned long long pack2(float x, float y) {
  unsigned long long r;
  asm("mov.b64 %0, {%1, %2};" : "=l"(r) : "f"(x), "f"(y));
  return r;
}
__device__ __forceinline__ float plo(unsigned long long v) {
  return __uint_as_float((unsigned)v);
}
__device__ __forceinline__ float phi(unsigned long long v) {
  return __uint_as_float((unsigned)(v >> 32));
}
__device__ __forceinline__ float sigm(float x) {
  return __fdividef(1.f, 1.f + __expf(-x));
}
__device__ __forceinline__ float ftanh(float x) {
  float e = __expf(-2.f * fmaxf(x, -20.f));
  return __fdividef(1.f - e, 1.f + e);
}

#define CLUSTER_SYNC()                                              \
  do {                                                              \
    asm volatile("barrier.cluster.arrive.aligned;" ::: "memory");   \
    asm volatile("barrier.cluster.wait.aligned;" ::: "memory");     \
  } while (0)

// ------------------- profiling-window shim (no-op kernel) ------------------
// Three launched BEFORE gemm_xw_k so the fixed ncu window (our 4th launch)
// captures gemm_xw_k this round.
__global__ void dummy_k() {}

// ------------- 1) fused embedding + input GEMM: xW = X @ Wih^T + b ---------
__global__ void __launch_bounds__(256) gemm_xw_k(
    const int* __restrict__ sentence, const float* __restrict__ table,
    const float* __restrict__ Wf, const float* __restrict__ Wb,
    const float* __restrict__ bihf, const float* __restrict__ bhhf,
    const float* __restrict__ bihb, const float* __restrict__ bhhb) {
  __shared__ __align__(16) unsigned long long As2[32 * 128];  // [k][m] dup
  __shared__ __align__(16) float Bs[32 * 68];                 // [k][n] padded
  int tid = threadIdx.x;
  int bm = blockIdx.x, bn = blockIdx.y;
  int r0 = bm * 128, n0 = bn * 64;
  int tx = tid & 15, ty = tid >> 4;

  int arow = tid >> 1, akh = (tid & 1) * 16;
  int r = r0 + arow;
  int s = r >> 7, b = r & 127;
  const float* asrc = table + (size_t)sentence[b * SS + s] * EE;
  int brow = tid >> 2, bkq = (tid & 3) * 8;
  int jg = n0 + brow;
  const float* wsrc = (jg < 512) ? Wf + (size_t)jg * EE
                                 : Wb + (size_t)(jg - 512) * EE;

  unsigned long long acc2[8][2];
#pragma unroll
  for (int i = 0; i < 8; i++) { acc2[i][0] = 0ull; acc2[i][1] = 0ull; }

  for (int kt = 0; kt < 4; kt++) {
    int kb = kt * 32;
#pragma unroll
    for (int q = 0; q < 4; q++) {
      float4 v = *(const float4*)(asrc + kb + akh + q * 4);
      As2[(akh + q * 4 + 0) * 128 + arow] = pack2(v.x, v.x);
      As2[(akh + q * 4 + 1) * 128 + arow] = pack2(v.y, v.y);
      As2[(akh + q * 4 + 2) * 128 + arow] = pack2(v.z, v.z);
      As2[(akh + q * 4 + 3) * 128 + arow] = pack2(v.w, v.w);
    }
#pragma unroll
    for (int q = 0; q < 2; q++) {
      float4 v = *(const float4*)(wsrc + kb + bkq + q * 4);
      Bs[(bkq + q * 4 + 0) * 68 + brow] = v.x;
      Bs[(bkq + q * 4 + 1) * 68 + brow] = v.y;
      Bs[(bkq + q * 4 + 2) * 68 + brow] = v.z;
      Bs[(bkq + q * 4 + 3) * 68 + brow] = v.w;
    }
    __syncthreads();
#pragma unroll
    for (int kk = 0; kk < 32; kk++) {
      ulonglong2 a01 = *(const ulonglong2*)&As2[kk * 128 + ty * 8 + 0];
      ulonglong2 a23 = *(const ulonglong2*)&As2[kk * 128 + ty * 8 + 2];
      ulonglong2 a45 = *(const ulonglong2*)&As2[kk * 128 + ty * 8 + 4];
      ulonglong2 a67 = *(const ulonglong2*)&As2[kk * 128 + ty * 8 + 6];
      ulonglong2 bp = *(const ulonglong2*)&Bs[kk * 68 + tx * 4];
      fma2(acc2[0][0], a01.x, bp.x); fma2(acc2[0][1], a01.x, bp.y);
      fma2(acc2[1][0], a01.y, bp.x); fma2(acc2[1][1], a01.y, bp.y);
      fma2(acc2[2][0], a23.x, bp.x); fma2(acc2[2][1], a23.x, bp.y);
      fma2(acc2[3][0], a23.y, bp.x); fma2(acc2[3][1], a23.y, bp.y);
      fma2(acc2[4][0], a45.x, bp.x); fma2(acc2[4][1], a45.x, bp.y);
      fma2(acc2[5][0], a45.y, bp.x); fma2(acc2[5][1], a45.y, bp.y);
      fma2(acc2[6][0], a67.x, bp.x); fma2(acc2[6][1], a67.x, bp.y);
      fma2(acc2[7][0], a67.y, bp.x); fma2(acc2[7][1], a67.y, bp.y);
    }
    __syncthreads();
  }
  float bias[4];
#pragma unroll
  for (int jj = 0; jj < 4; jj++) {
    int j = n0 + tx * 4 + jj;
    bias[jj] = (j < 512) ? (bihf[j] + bhhf[j]) : (bihb[j - 512] + bhhb[j - 512]);
  }
  int n = n0 + tx * 4;
#pragma unroll
  for (int ii = 0; ii < 8; ii++) {
    int m = r0 + ty * 8 + ii;
    float4 o;
    o.x = plo(acc2[ii][0]) + bias[0];
    o.y = phi(acc2[ii][0]) + bias[1];
    o.z = plo(acc2[ii][1]) + bias[2];
    o.w = phi(acc2[ii][1]) + bias[3];
    *(float4*)&g_xW[(size_t)m * 1024 + n] = o;
  }
}

// --------------- 2) bidirectional LSTM recurrence (cluster pairs) ----------
// R6 configuration — best measured (895us). 64 clusters of 2 CTAs; cluster =
// (dir, 4-batch tile); CTA = u-half. W_hh register-resident; h exchanged via
// DSMEM store + one 16-arrival phase-parity mbarrier per step.
__global__ void __cluster_dims__(2, 1, 1) __launch_bounds__(256, 1) lstm_k(
    const float* __restrict__ Whhf, const float* __restrict__ Whhb,
    const float* __restrict__ h0, const float* __restrict__ c0) {
  __shared__ __align__(16) float hb[2][4 * 132];  // [parity][b_local*132 + u]
  __shared__ __align__(8) unsigned long long bar;
  int rank = blockIdx.x & 1;
  int cl = blockIdx.x >> 1;
  int d = cl >> 5;
  int b0 = (cl & 31) * 4;
  int tid = threadIdx.x;
  int lane = tid & 31;
  int wid = tid >> 5;
  int ks = lane >> 3;                 // k-slice 0..3
  int ulg = wid * 8 + (lane & 7);     // 0..63
  int u = rank * 64 + ulg;

  const float* Whh = d ? Whhb : Whhf;
  unsigned long long w2[4][16];
#pragma unroll
  for (int g = 0; g < 4; g++) {
    const float* wr = Whh + (size_t)(g * 128 + u) * 128 + ks * 32;
#pragma unroll
    for (int q = 0; q < 8; q++) {
      ulonglong2 v = *(const ulonglong2*)(wr + q * 4);
      w2[g][q * 2] = v.x;
      w2[g][q * 2 + 1] = v.y;
    }
  }
  for (int i = tid; i < 512; i += 256) {
    int j = i >> 7, uu = i & 127;
    hb[0][j * 132 + uu] = h0[(d * BB + b0 + j) * HH + uu];
  }
  float c = c0[(d * BB + b0 + ks) * HH + u];

  unsigned hb_u32, bar_u32;
  asm("{ .reg .u64 t; cvta.to.shared.u64 t, %1; cvt.u32.u64 %0, t; }"
      : "=r"(hb_u32) : "l"(&hb[0][0]));
  asm("{ .reg .u64 t; cvta.to.shared.u64 t, %1; cvt.u32.u64 %0, t; }"
      : "=r"(bar_u32) : "l"(&bar));
  unsigned peer_base, peer_bar;
  asm("mapa.shared::cluster.u32 %0, %1, %2;"
      : "=r"(peer_base) : "r"(hb_u32), "r"(rank ^ 1));
  asm("mapa.shared::cluster.u32 %0, %1, %2;"
      : "=r"(peer_bar) : "r"(bar_u32), "r"(rank ^ 1));

  if (tid == 0) {
    asm volatile("mbarrier.init.shared.b64 [%0], 16;" :: "r"(bar_u32)
                 : "memory");
  }
  __syncthreads();
  CLUSTER_SYNC();  // mbarrier init visible cluster-wide before any arrive

  for (int t = 0; t < SS; t++) {
    const float* cur = hb[t & 1];
    int np = (t + 1) & 1;
    int tx = d ? (SS - 1 - t) : t;
    float xwv[4];
    const float* xwb =
        g_xW + ((size_t)tx * BB + b0) * 1024 + d * 512 + ks * 128 + u;
#pragma unroll
    for (int j = 0; j < 4; j++) xwv[j] = __ldcg(xwb + j * 1024);

    unsigned long long acc2[4][4];
#pragma unroll
    for (int j = 0; j < 4; j++)
#pragma unroll
      for (int g = 0; g < 4; g++) acc2[j][g] = 0ull;

#pragma unroll
    for (int q = 0; q < 8; q++) {
      int k = ks * 32 + q * 4;
      ulonglong2 hv[4];
#pragma unroll
      for (int j = 0; j < 4; j++)
        hv[j] = *(const ulonglong2*)&cur[j * 132 + k];
#pragma unroll
      for (int j = 0; j < 4; j++)
#pragma unroll
        for (int g = 0; g < 4; g++) {
          fma2(acc2[j][g], hv[j].x, w2[g][q * 2]);
          fma2(acc2[j][g], hv[j].y, w2[g][q * 2 + 1]);
        }
    }
    float acc[4][4];
#pragma unroll
    for (int j = 0; j < 4; j++)
#pragma unroll
      for (int g = 0; g < 4; g++) {
        float v = plo(acc2[j][g]) + phi(acc2[j][g]);
        if (g == ks) v += xwv[j];
        v += __shfl_xor_sync(0xffffffffu, v, 8);
        v += __shfl_xor_sync(0xffffffffu, v, 16);
        acc[j][g] = v;
      }
    float gate[4];
#pragma unroll
    for (int g = 0; g < 4; g++) {
      float a01 = (ks & 1) ? acc[1][g] : acc[0][g];
      float a23 = (ks & 1) ? acc[3][g] : acc[2][g];
      gate[g] = (ks & 2) ? a23 : a01;
    }
    float si = sigm(gate[0]);
    float sf = sigm(gate[1]);
    float tg = ftanh(gate[2]);
    float so = sigm(gate[3]);
    c = sf * c + si * tg;
    float h = so * ftanh(c);
    hb[np][ks * 132 + u] = h;
    unsigned pa = peer_base + (unsigned)(np * 528 + ks * 132 + u) * 4u;
    asm volatile("st.shared::cluster.f32 [%0], %1;" :: "r"(pa), "f"(h));
    g_hs[d][((size_t)tx * BB + b0 + ks) * HH + u] = h;

    __syncwarp();
    if (lane == 0) {
      asm volatile("mbarrier.arrive.release.cta.shared::cta.b64 _, [%0];"
                   :: "r"(bar_u32) : "memory");
      asm volatile(
          "mbarrier.arrive.release.cluster.shared::cluster.b64 _, [%0];"
          :: "r"(peer_bar) : "memory");
    }
    {
      unsigned parity = (unsigned)(t & 1);
      asm volatile(
          "{\n\t"
          ".reg .pred P;\n\t"
          "WL_%=:\n\t"
          "mbarrier.try_wait.parity.acquire.cluster.shared::cta.b64 P, [%0], %1, 0x989680;\n\t"
          "@P bra.uni WD_%=;\n\t"
          "bra.uni WL_%=;\n\t"
          "WD_%=:\n\t"
          "}"
          :: "r"(bar_u32), "r"(parity) : "memory");
    }
  }
}

// -------------- 3) feats = concat(hf,hb) @ Wout^T + bout -------------------
__global__ void __launch_bounds__(256) feats_k(const float* __restrict__ Wout,
                                               const float* __restrict__ bout) {
  __shared__ __align__(16) float Wsh[32 * 260];
  __shared__ float bsh[32];
  int s = blockIdx.x;
  int tid = threadIdx.x;
  for (int i = tid; i < 2048; i += 256) {
    int k = i >> 6, m4 = i & 63;
    float4 v = ((const float4*)Wout)[i];
    *(float4*)&Wsh[k * 260 + m4 * 4] = v;
  }
  if (tid < 32) bsh[tid] = bout[tid];
  __syncthreads();
  int k = tid & 31, b0 = tid >> 5;
  for (int bb = 0; bb < 16; bb++) {
    int b = b0 + bb * 8;
    const float4* hf = (const float4*)&g_hs[0][((size_t)s * BB + b) * HH];
    const float4* hb2 = (const float4*)&g_hs[1][((size_t)s * BB + b) * HH];
    float acc = bsh[k];
#pragma unroll 8
    for (int m4 = 0; m4 < 32; m4++) {
      float4 hv = hf[m4];
      float4 wv = *(const float4*)&Wsh[k * 260 + m4 * 4];
      acc += hv.x * wv.x + hv.y * wv.y + hv.z * wv.z + hv.w * wv.w;
    }
#pragma unroll 8
    for (int m4 = 0; m4 < 32; m4++) {
      float4 hv = hb2[m4];
      float4 wv = *(const float4*)&Wsh[k * 260 + 128 + m4 * 4];
      acc += hv.x * wv.x + hv.y * wv.y + hv.z * wv.z + hv.w * wv.w;
    }
    g_feats[((size_t)b * SS + s) * KK + k] = acc;
  }
}

// ----------------------------- 4) CRF numerator ----------------------------
__global__ void __launch_bounds__(128) numer_k(const int* __restrict__ tags,
                                               const float* __restrict__ T) {
  __shared__ float red[128];
  int b = blockIdx.x;
  int tid = threadIdx.x;
  float sum = 0.f;
  for (int s = tid; s < SS; s += 128) {
    int cur = tags[b * SS + s];
    int prev = (s == 0) ? TAG_START : tags[b * SS + s - 1];
    sum += T[prev * KK + cur] + g_feats[((size_t)b * SS + s) * KK + cur];
  }
  red[tid] = sum;
  __syncthreads();
  for (int off = 64; off > 0; off >>= 1) {
    if (tid < off) red[tid] += red[tid + off];
    __syncthreads();
  }
  if (tid == 0) g_num[b] = red[0] + T[tags[b * SS + SS - 1] * KK + TAG_END];
}

// ---------------------------- 5) CRF denominator ---------------------------
// one warp per batch row; lane = next-tag. Step 0 in log space (alpha spread
// is 1e4 there; exp space would underflow to S=0). Then convert to a
// NORMALIZED EXP-SPACE scan: true_alpha[n] = logacc + log(a[n]).
//   t[n]   = sum_p a[p] * expT[n][p]     (4 independent FMA chains)
//   u[n]   = t[n] * exp(feat[n])
//   S      = sum_n u[n];  a = u/S;  logacc += log(S)
// No per-step max-reduce or exp(alpha-m) needed; expT[n][START]=0 and the
// END row = 0 preserve the reference's -1e4 masking exactly.
__global__ void __launch_bounds__(256) denom_k(const float* __restrict__ T) {
  __shared__ float Tsh[32 * 33];
  int tid = threadIdx.x;
  int lane = tid & 31;
  int warp = tid >> 5;
  int b = blockIdx.x * 8 + warp;
  for (int i = tid; i < 1024; i += 256) Tsh[(i >> 5) * 33 + (i & 31)] = T[i];
  __syncthreads();

  const float* Trow = &Tsh[lane * 33];
  float alpha = (lane == TAG_START) ? 0.f : -10000.f;

  // step 0: safe two-pass log-space logsumexp
  {
    float feat = g_feats[(size_t)b * SS * KK + lane];
    float tmp[32];
    float m = -3.0e38f;
#pragma unroll
    for (int p = 0; p < 32; p++) {
      float ap = __shfl_sync(0xffffffffu, alpha, p);
      tmp[p] = ap + Trow[p];
      m = fmaxf(m, tmp[p]);
    }
    float sum = 0.f;
#pragma unroll
    for (int p = 0; p < 32; p++) sum += __expf(tmp[p] - m);
    alpha = __logf(sum) + m + feat;
  }

  // convert to normalized exp space
  float m0 = alpha;
#pragma unroll
  for (int o = 16; o > 0; o >>= 1)
    m0 = fmaxf(m0, __shfl_xor_sync(0xffffffffu, m0, o));
  float a = __expf(alpha - m0);
  float logacc = m0;

  // register-resident exp(T) row
  float rTe[32];
#pragma unroll
  for (int p = 0; p < 32; p++) rTe[p] = __expf(Trow[p]);

  float feat_next = g_feats[((size_t)b * SS + 1) * KK + lane];
  for (int s = 1; s < SS; s++) {
    float feat = feat_next;
    if (s + 1 < SS) feat_next = g_feats[((size_t)b * SS + s + 1) * KK + lane];
    float ef = __expf(feat);
    float t0 = 0.f, t1 = 0.f, t2 = 0.f, t3 = 0.f;
#pragma unroll
    for (int p = 0; p < 32; p += 4) {
      t0 = fmaf(__shfl_sync(0xffffffffu, a, p + 0), rTe[p + 0], t0);
      t1 = fmaf(__shfl_sync(0xffffffffu, a, p + 1), rTe[p + 1], t1);
      t2 = fmaf(__shfl_sync(0xffffffffu, a, p + 2), rTe[p + 2], t2);
      t3 = fmaf(__shfl_sync(0xffffffffu, a, p + 3), rTe[p + 3], t3);
    }
    float u = ((t0 + t1) + (t2 + t3)) * ef;
    float S = u;
#pragma unroll
    for (int o = 16; o > 0; o >>= 1) S += __shfl_xor_sync(0xffffffffu, S, o);
    a = __fdividef(u, S);
    logacc += __logf(S);
  }
  // finish: den = logacc + log( sum_n a[n] * exp(T[n, END]) )
  float v = a * __expf(Trow[TAG_END]);
#pragma unroll
  for (int o = 16; o > 0; o >>= 1) v += __shfl_xor_sync(0xffffffffu, v, o);
  if (lane == 0) g_den[b] = logacc + __logf(v);
}

// --------------------------------- 6) mean ---------------------------------
__global__ void __launch_bounds__(128) mean_k(float* __restrict__ out) {
  __shared__ float red[128];
  int tid = threadIdx.x;
  red[tid] = g_num[tid] - g_den[tid];
  __syncthreads();
  for (int off = 64; off > 0; off >>= 1) {
    if (tid < off) red[tid] += red[tid + off];
    __syncthreads();
  }
  if (tid == 0) out[0] = red[0] / 128.0f;
}

// ------------------------------- launcher ----------------------------------
extern "C" void kernel_launch(void* const* d_in, const int* in_sizes, int n_in,
                              void* d_out, int out_size) {
  const int*   sentence = (const int*)d_in[0];
  const int*   tags     = (const int*)d_in[1];
  const float* table    = (const float*)d_in[2];
  const float* W_ih_f   = (const float*)d_in[3];
  const float* W_hh_f   = (const float*)d_in[4];
  const float* b_ih_f   = (const float*)d_in[5];
  const float* b_hh_f   = (const float*)d_in[6];
  const float* W_ih_b   = (const float*)d_in[7];
  const float* W_hh_b   = (const float*)d_in[8];
  const float* b_ih_b   = (const float*)d_in[9];
  const float* b_hh_b   = (const float*)d_in[10];
  const float* W_out    = (const float*)d_in[11];
  const float* b_out    = (const float*)d_in[12];
  const float* trans    = (const float*)d_in[13];
  const float* h0       = (const float*)d_in[14];
  const float* c0       = (const float*)d_in[15];
  float* out = (float*)d_out;

  // shift the fixed ncu capture window (our 4th launch) onto gemm_xw_k
  dummy_k<<<1, 32>>>();
  dummy_k<<<1, 32>>>();
  dummy_k<<<1, 32>>>();
  gemm_xw_k<<<dim3(512, 16), 256>>>(sentence, table, W_ih_f, W_ih_b,
                                    b_ih_f, b_hh_f, b_ih_b, b_hh_b);
  lstm_k<<<128, 256>>>(W_hh_f, W_hh_b, h0, c0);
  feats_k<<<512, 256>>>(W_out, b_out);
  numer_k<<<128, 128>>>(tags, trans);
  denom_k<<<16, 256>>>(trans);
  mean_k<<<1, 128>>>(out);
}

// round 12
// speedup vs baseline: 1.1265x; 1.0217x over previous
#include <cuda_runtime.h>
#include <cuda_bf16.h>
#include <math.h>

#define SS 512
#define BB 128
#define EE 128
#define HH 128
#define KK 32
#define TAG_START 30
#define TAG_END 31

// ----------------------------- device scratch ------------------------------
__device__ float g_xW[(size_t)SS * BB * 1024];   // [s*B+b][d*512 + g*128 + u]
__device__ float g_hs[2][(size_t)SS * BB * HH];  // per-dir h at original time
__device__ float g_feats[(size_t)BB * SS * KK];  // [b][s][k]
__device__ float g_num[BB];
__device__ float g_den[BB];

// ----------------------------- helpers -------------------------------------
__device__ __forceinline__ void fma2(unsigned long long& d, unsigned long long a,
                                     unsigned long long b) {
  asm("fma.rn.f32x2 %0, %1, %2, %0;" : "+l"(d) : "l"(a), "l"(b));
}
__device__ __forceinline__ unsigned long long pack2(float x, float y) {
  unsigned long long r;
  asm("mov.b64 %0, {%1, %2};" : "=l"(r) : "f"(x), "f"(y));
  return r;
}
__device__ __forceinline__ float plo(unsigned long long v) {
  return __uint_as_float((unsigned)v);
}
__device__ __forceinline__ float phi(unsigned long long v) {
  return __uint_as_float((unsigned)(v >> 32));
}
__device__ __forceinline__ float sigm(float x) {
  return __fdividef(1.f, 1.f + __expf(-x));
}
__device__ __forceinline__ float ftanh(float x) {
  float e = __expf(-2.f * fmaxf(x, -20.f));
  return __fdividef(1.f - e, 1.f + e);
}

#define CLUSTER_SYNC()                                              \
  do {                                                              \
    asm volatile("barrier.cluster.arrive.aligned;" ::: "memory");   \
    asm volatile("barrier.cluster.wait.aligned;" ::: "memory");     \
  } while (0)

// ------------------- profiling-window shim (no-op kernel) ------------------
// Three launched BEFORE gemm_xw_k so the fixed ncu window (our 4th launch)
// captures gemm_xw_k again this round (verify the wavefront theory).
__global__ void dummy_k() {}

// ------------- 1) fused embedding + input GEMM: xW = X @ Wih^T + b ---------
// M = S*B = 65536, N = 1024, K = 128. Block tile 128m x 128n, thread tile
// 8m x 8n, f32x2 packed FMA. R11 ncu: L1tex 92.7% (smem-wf bound) at 8m x 4n;
// doubling n per thread doubles FFMA2 per A-read -> wf demand drops below the
// FFMA2 issue floor. A staged pre-duplicated (a,a); B staged [k][n] so an
// 8-float read is 2 conflict-free LDS.128 yielding native (n0,n1) pairs.
__global__ void __launch_bounds__(256, 2) gemm_xw_k(
    const int* __restrict__ sentence, const float* __restrict__ table,
    const float* __restrict__ Wf, const float* __restrict__ Wb,
    const float* __restrict__ bihf, const float* __restrict__ bhhf,
    const float* __restrict__ bihb, const float* __restrict__ bhhb) {
  __shared__ __align__(16) unsigned long long As2[32 * 128];  // [k][m] dup
  __shared__ __align__(16) float Bs[32 * 132];                // [k][n] padded
  int tid = threadIdx.x;
  int bm = blockIdx.x, bn = blockIdx.y;
  int r0 = bm * 128, n0 = bn * 128;
  int tx = tid & 15, ty = tid >> 4;   // tx: n-octet 0..15, ty: m-octet 0..15

  // A loader: 2 threads per m-row, 16 k each
  int arow = tid >> 1, akh = (tid & 1) * 16;
  int r = r0 + arow;
  int s = r >> 7, b = r & 127;
  const float* asrc = table + (size_t)sentence[b * SS + s] * EE;
  // B loader: 2 threads per n-row, 16 k each
  int brow = tid >> 1, bkh = (tid & 1) * 16;
  int jg = n0 + brow;
  const float* wsrc = (jg < 512) ? Wf + (size_t)jg * EE
                                 : Wb + (size_t)(jg - 512) * EE;

  unsigned long long acc2[8][4];
#pragma unroll
  for (int i = 0; i < 8; i++)
#pragma unroll
    for (int p = 0; p < 4; p++) acc2[i][p] = 0ull;

  for (int kt = 0; kt < 4; kt++) {
    int kb = kt * 32;
#pragma unroll
    for (int q = 0; q < 4; q++) {
      float4 v = *(const float4*)(asrc + kb + akh + q * 4);
      As2[(akh + q * 4 + 0) * 128 + arow] = pack2(v.x, v.x);
      As2[(akh + q * 4 + 1) * 128 + arow] = pack2(v.y, v.y);
      As2[(akh + q * 4 + 2) * 128 + arow] = pack2(v.z, v.z);
      As2[(akh + q * 4 + 3) * 128 + arow] = pack2(v.w, v.w);
    }
#pragma unroll
    for (int q = 0; q < 4; q++) {
      float4 v = *(const float4*)(wsrc + kb + bkh + q * 4);
      Bs[(bkh + q * 4 + 0) * 132 + brow] = v.x;
      Bs[(bkh + q * 4 + 1) * 132 + brow] = v.y;
      Bs[(bkh + q * 4 + 2) * 132 + brow] = v.z;
      Bs[(bkh + q * 4 + 3) * 132 + brow] = v.w;
    }
    __syncthreads();
#pragma unroll
    for (int kk = 0; kk < 32; kk++) {
      ulonglong2 a01 = *(const ulonglong2*)&As2[kk * 128 + ty * 8 + 0];
      ulonglong2 a23 = *(const ulonglong2*)&As2[kk * 128 + ty * 8 + 2];
      ulonglong2 a45 = *(const ulonglong2*)&As2[kk * 128 + ty * 8 + 4];
      ulonglong2 a67 = *(const ulonglong2*)&As2[kk * 128 + ty * 8 + 6];
      ulonglong2 b03 = *(const ulonglong2*)&Bs[kk * 132 + tx * 8];
      ulonglong2 b47 = *(const ulonglong2*)&Bs[kk * 132 + tx * 8 + 4];
      fma2(acc2[0][0], a01.x, b03.x); fma2(acc2[0][1], a01.x, b03.y);
      fma2(acc2[0][2], a01.x, b47.x); fma2(acc2[0][3], a01.x, b47.y);
      fma2(acc2[1][0], a01.y, b03.x); fma2(acc2[1][1], a01.y, b03.y);
      fma2(acc2[1][2], a01.y, b47.x); fma2(acc2[1][3], a01.y, b47.y);
      fma2(acc2[2][0], a23.x, b03.x); fma2(acc2[2][1], a23.x, b03.y);
      fma2(acc2[2][2], a23.x, b47.x); fma2(acc2[2][3], a23.x, b47.y);
      fma2(acc2[3][0], a23.y, b03.x); fma2(acc2[3][1], a23.y, b03.y);
      fma2(acc2[3][2], a23.y, b47.x); fma2(acc2[3][3], a23.y, b47.y);
      fma2(acc2[4][0], a45.x, b03.x); fma2(acc2[4][1], a45.x, b03.y);
      fma2(acc2[4][2], a45.x, b47.x); fma2(acc2[4][3], a45.x, b47.y);
      fma2(acc2[5][0], a45.y, b03.x); fma2(acc2[5][1], a45.y, b03.y);
      fma2(acc2[5][2], a45.y, b47.x); fma2(acc2[5][3], a45.y, b47.y);
      fma2(acc2[6][0], a67.x, b03.x); fma2(acc2[6][1], a67.x, b03.y);
      fma2(acc2[6][2], a67.x, b47.x); fma2(acc2[6][3], a67.x, b47.y);
      fma2(acc2[7][0], a67.y, b03.x); fma2(acc2[7][1], a67.y, b03.y);
      fma2(acc2[7][2], a67.y, b47.x); fma2(acc2[7][3], a67.y, b47.y);
    }
    __syncthreads();
  }
  float bias[8];
#pragma unroll
  for (int jj = 0; jj < 8; jj++) {
    int j = n0 + tx * 8 + jj;
    bias[jj] = (j < 512) ? (bihf[j] + bhhf[j]) : (bihb[j - 512] + bhhb[j - 512]);
  }
  int n = n0 + tx * 8;
#pragma unroll
  for (int ii = 0; ii < 8; ii++) {
    int m = r0 + ty * 8 + ii;
    float4 o0, o1;
    o0.x = plo(acc2[ii][0]) + bias[0];
    o0.y = phi(acc2[ii][0]) + bias[1];
    o0.z = plo(acc2[ii][1]) + bias[2];
    o0.w = phi(acc2[ii][1]) + bias[3];
    o1.x = plo(acc2[ii][2]) + bias[4];
    o1.y = phi(acc2[ii][2]) + bias[5];
    o1.z = plo(acc2[ii][3]) + bias[6];
    o1.w = phi(acc2[ii][3]) + bias[7];
    *(float4*)&g_xW[(size_t)m * 1024 + n] = o0;
    *(float4*)&g_xW[(size_t)m * 1024 + n + 4] = o1;
  }
}

// --------------- 2) bidirectional LSTM recurrence (cluster pairs) ----------
// R6 configuration — best measured (895us). 64 clusters of 2 CTAs; cluster =
// (dir, 4-batch tile); CTA = u-half. W_hh register-resident; h exchanged via
// DSMEM store + one 16-arrival phase-parity mbarrier per step.
__global__ void __cluster_dims__(2, 1, 1) __launch_bounds__(256, 1) lstm_k(
    const float* __restrict__ Whhf, const float* __restrict__ Whhb,
    const float* __restrict__ h0, const float* __restrict__ c0) {
  __shared__ __align__(16) float hb[2][4 * 132];  // [parity][b_local*132 + u]
  __shared__ __align__(8) unsigned long long bar;
  int rank = blockIdx.x & 1;
  int cl = blockIdx.x >> 1;
  int d = cl >> 5;
  int b0 = (cl & 31) * 4;
  int tid = threadIdx.x;
  int lane = tid & 31;
  int wid = tid >> 5;
  int ks = lane >> 3;                 // k-slice 0..3
  int ulg = wid * 8 + (lane & 7);     // 0..63
  int u = rank * 64 + ulg;

  const float* Whh = d ? Whhb : Whhf;
  unsigned long long w2[4][16];
#pragma unroll
  for (int g = 0; g < 4; g++) {
    const float* wr = Whh + (size_t)(g * 128 + u) * 128 + ks * 32;
#pragma unroll
    for (int q = 0; q < 8; q++) {
      ulonglong2 v = *(const ulonglong2*)(wr + q * 4);
      w2[g][q * 2] = v.x;
      w2[g][q * 2 + 1] = v.y;
    }
  }
  for (int i = tid; i < 512; i += 256) {
    int j = i >> 7, uu = i & 127;
    hb[0][j * 132 + uu] = h0[(d * BB + b0 + j) * HH + uu];
  }
  float c = c0[(d * BB + b0 + ks) * HH + u];

  unsigned hb_u32, bar_u32;
  asm("{ .reg .u64 t; cvta.to.shared.u64 t, %1; cvt.u32.u64 %0, t; }"
      : "=r"(hb_u32) : "l"(&hb[0][0]));
  asm("{ .reg .u64 t; cvta.to.shared.u64 t, %1; cvt.u32.u64 %0, t; }"
      : "=r"(bar_u32) : "l"(&bar));
  unsigned peer_base, peer_bar;
  asm("mapa.shared::cluster.u32 %0, %1, %2;"
      : "=r"(peer_base) : "r"(hb_u32), "r"(rank ^ 1));
  asm("mapa.shared::cluster.u32 %0, %1, %2;"
      : "=r"(peer_bar) : "r"(bar_u32), "r"(rank ^ 1));

  if (tid == 0) {
    asm volatile("mbarrier.init.shared.b64 [%0], 16;" :: "r"(bar_u32)
                 : "memory");
  }
  __syncthreads();
  CLUSTER_SYNC();  // mbarrier init visible cluster-wide before any arrive

  for (int t = 0; t < SS; t++) {
    const float* cur = hb[t & 1];
    int np = (t + 1) & 1;
    int tx = d ? (SS - 1 - t) : t;
    float xwv[4];
    const float* xwb =
        g_xW + ((size_t)tx * BB + b0) * 1024 + d * 512 + ks * 128 + u;
#pragma unroll
    for (int j = 0; j < 4; j++) xwv[j] = __ldcg(xwb + j * 1024);

    unsigned long long acc2[4][4];
#pragma unroll
    for (int j = 0; j < 4; j++)
#pragma unroll
      for (int g = 0; g < 4; g++) acc2[j][g] = 0ull;

#pragma unroll
    for (int q = 0; q < 8; q++) {
      int k = ks * 32 + q * 4;
      ulonglong2 hv[4];
#pragma unroll
      for (int j = 0; j < 4; j++)
        hv[j] = *(const ulonglong2*)&cur[j * 132 + k];
#pragma unroll
      for (int j = 0; j < 4; j++)
#pragma unroll
        for (int g = 0; g < 4; g++) {
          fma2(acc2[j][g], hv[j].x, w2[g][q * 2]);
          fma2(acc2[j][g], hv[j].y, w2[g][q * 2 + 1]);
        }
    }
    float acc[4][4];
#pragma unroll
    for (int j = 0; j < 4; j++)
#pragma unroll
      for (int g = 0; g < 4; g++) {
        float v = plo(acc2[j][g]) + phi(acc2[j][g]);
        if (g == ks) v += xwv[j];
        v += __shfl_xor_sync(0xffffffffu, v, 8);
        v += __shfl_xor_sync(0xffffffffu, v, 16);
        acc[j][g] = v;
      }
    float gate[4];
#pragma unroll
    for (int g = 0; g < 4; g++) {
      float a01 = (ks & 1) ? acc[1][g] : acc[0][g];
      float a23 = (ks & 1) ? acc[3][g] : acc[2][g];
      gate[g] = (ks & 2) ? a23 : a01;
    }
    float si = sigm(gate[0]);
    float sf = sigm(gate[1]);
    float tg = ftanh(gate[2]);
    float so = sigm(gate[3]);
    c = sf * c + si * tg;
    float h = so * ftanh(c);
    hb[np][ks * 132 + u] = h;
    unsigned pa = peer_base + (unsigned)(np * 528 + ks * 132 + u) * 4u;
    asm volatile("st.shared::cluster.f32 [%0], %1;" :: "r"(pa), "f"(h));
    g_hs[d][((size_t)tx * BB + b0 + ks) * HH + u] = h;

    __syncwarp();
    if (lane == 0) {
      asm volatile("mbarrier.arrive.release.cta.shared::cta.b64 _, [%0];"
                   :: "r"(bar_u32) : "memory");
      asm volatile(
          "mbarrier.arrive.release.cluster.shared::cluster.b64 _, [%0];"
          :: "r"(peer_bar) : "memory");
    }
    {
      unsigned parity = (unsigned)(t & 1);
      asm volatile(
          "{\n\t"
          ".reg .pred P;\n\t"
          "WL_%=:\n\t"
          "mbarrier.try_wait.parity.acquire.cluster.shared::cta.b64 P, [%0], %1, 0x989680;\n\t"
          "@P bra.uni WD_%=;\n\t"
          "bra.uni WL_%=;\n\t"
          "WD_%=:\n\t"
          "}"
          :: "r"(bar_u32), "r"(parity) : "memory");
    }
  }
}

// -------------- 3) feats = concat(hf,hb) @ Wout^T + bout -------------------
__global__ void __launch_bounds__(256) feats_k(const float* __restrict__ Wout,
                                               const float* __restrict__ bout) {
  __shared__ __align__(16) float Wsh[32 * 260];
  __shared__ float bsh[32];
  int s = blockIdx.x;
  int tid = threadIdx.x;
  for (int i = tid; i < 2048; i += 256) {
    int k = i >> 6, m4 = i & 63;
    float4 v = ((const float4*)Wout)[i];
    *(float4*)&Wsh[k * 260 + m4 * 4] = v;
  }
  if (tid < 32) bsh[tid] = bout[tid];
  __syncthreads();
  int k = tid & 31, b0 = tid >> 5;
  for (int bb = 0; bb < 16; bb++) {
    int b = b0 + bb * 8;
    const float4* hf = (const float4*)&g_hs[0][((size_t)s * BB + b) * HH];
    const float4* hb2 = (const float4*)&g_hs[1][((size_t)s * BB + b) * HH];
    float acc = bsh[k];
#pragma unroll 8
    for (int m4 = 0; m4 < 32; m4++) {
      float4 hv = hf[m4];
      float4 wv = *(const float4*)&Wsh[k * 260 + m4 * 4];
      acc += hv.x * wv.x + hv.y * wv.y + hv.z * wv.z + hv.w * wv.w;
    }
#pragma unroll 8
    for (int m4 = 0; m4 < 32; m4++) {
      float4 hv = hb2[m4];
      float4 wv = *(const float4*)&Wsh[k * 260 + 128 + m4 * 4];
      acc += hv.x * wv.x + hv.y * wv.y + hv.z * wv.z + hv.w * wv.w;
    }
    g_feats[((size_t)b * SS + s) * KK + k] = acc;
  }
}

// ----------------------------- 4) CRF numerator ----------------------------
__global__ void __launch_bounds__(128) numer_k(const int* __restrict__ tags,
                                               const float* __restrict__ T) {
  __shared__ float red[128];
  int b = blockIdx.x;
  int tid = threadIdx.x;
  float sum = 0.f;
  for (int s = tid; s < SS; s += 128) {
    int cur = tags[b * SS + s];
    int prev = (s == 0) ? TAG_START : tags[b * SS + s - 1];
    sum += T[prev * KK + cur] + g_feats[((size_t)b * SS + s) * KK + cur];
  }
  red[tid] = sum;
  __syncthreads();
  for (int off = 64; off > 0; off >>= 1) {
    if (tid < off) red[tid] += red[tid + off];
    __syncthreads();
  }
  if (tid == 0) g_num[b] = red[0] + T[tags[b * SS + SS - 1] * KK + TAG_END];
}

// ---------------------------- 5) CRF denominator ---------------------------
// normalized exp-space scan (R11, verified rel_err 7.1e-7).
__global__ void __launch_bounds__(256) denom_k(const float* __restrict__ T) {
  __shared__ float Tsh[32 * 33];
  int tid = threadIdx.x;
  int lane = tid & 31;
  int warp = tid >> 5;
  int b = blockIdx.x * 8 + warp;
  for (int i = tid; i < 1024; i += 256) Tsh[(i >> 5) * 33 + (i & 31)] = T[i];
  __syncthreads();

  const float* Trow = &Tsh[lane * 33];
  float alpha = (lane == TAG_START) ? 0.f : -10000.f;

  {
    float feat = g_feats[(size_t)b * SS * KK + lane];
    float tmp[32];
    float m = -3.0e38f;
#pragma unroll
    for (int p = 0; p < 32; p++) {
      float ap = __shfl_sync(0xffffffffu, alpha, p);
      tmp[p] = ap + Trow[p];
      m = fmaxf(m, tmp[p]);
    }
    float sum = 0.f;
#pragma unroll
    for (int p = 0; p < 32; p++) sum += __expf(tmp[p] - m);
    alpha = __logf(sum) + m + feat;
  }

  float m0 = alpha;
#pragma unroll
  for (int o = 16; o > 0; o >>= 1)
    m0 = fmaxf(m0, __shfl_xor_sync(0xffffffffu, m0, o));
  float a = __expf(alpha - m0);
  float logacc = m0;

  float rTe[32];
#pragma unroll
  for (int p = 0; p < 32; p++) rTe[p] = __expf(Trow[p]);

  float feat_next = g_feats[((size_t)b * SS + 1) * KK + lane];
  for (int s = 1; s < SS; s++) {
    float feat = feat_next;
    if (s + 1 < SS) feat_next = g_feats[((size_t)b * SS + s + 1) * KK + lane];
    float ef = __expf(feat);
    float t0 = 0.f, t1 = 0.f, t2 = 0.f, t3 = 0.f;
#pragma unroll
    for (int p = 0; p < 32; p += 4) {
      t0 = fmaf(__shfl_sync(0xffffffffu, a, p + 0), rTe[p + 0], t0);
      t1 = fmaf(__shfl_sync(0xffffffffu, a, p + 1), rTe[p + 1], t1);
      t2 = fmaf(__shfl_sync(0xffffffffu, a, p + 2), rTe[p + 2], t2);
      t3 = fmaf(__shfl_sync(0xffffffffu, a, p + 3), rTe[p + 3], t3);
    }
    float u = ((t0 + t1) + (t2 + t3)) * ef;
    float S = u;
#pragma unroll
    for (int o = 16; o > 0; o >>= 1) S += __shfl_xor_sync(0xffffffffu, S, o);
    a = __fdividef(u, S);
    logacc += __logf(S);
  }
  float v = a * __expf(Trow[TAG_END]);
#pragma unroll
  for (int o = 16; o > 0; o >>= 1) v += __shfl_xor_sync(0xffffffffu, v, o);
  if (lane == 0) g_den[b] = logacc + __logf(v);
}

// --------------------------------- 6) mean ---------------------------------
__global__ void __launch_bounds__(128) mean_k(float* __restrict__ out) {
  __shared__ float red[128];
  int tid = threadIdx.x;
  red[tid] = g_num[tid] - g_den[tid];
  __syncthreads();
  for (int off = 64; off > 0; off >>= 1) {
    if (tid < off) red[tid] += red[tid + off];
    __syncthreads();
  }
  if (tid == 0) out[0] = red[0] / 128.0f;
}

// ------------------------------- launcher ----------------------------------
extern "C" void kernel_launch(void* const* d_in, const int* in_sizes, int n_in,
                              void* d_out, int out_size) {
  const int*   sentence = (const int*)d_in[0];
  const int*   tags     = (const int*)d_in[1];
  const float* table    = (const float*)d_in[2];
  const float* W_ih_f   = (const float*)d_in[3];
  const float* W_hh_f   = (const float*)d_in[4];
  const float* b_ih_f   = (const float*)d_in[5];
  const float* b_hh_f   = (const float*)d_in[6];
  const float* W_ih_b   = (const float*)d_in[7];
  const float* W_hh_b   = (const float*)d_in[8];
  const float* b_ih_b   = (const float*)d_in[9];
  const float* b_hh_b   = (const float*)d_in[10];
  const float* W_out    = (const float*)d_in[11];
  const float* b_out    = (const float*)d_in[12];
  const float* trans    = (const float*)d_in[13];
  const float* h0       = (const float*)d_in[14];
  const float* c0       = (const float*)d_in[15];
  float* out = (float*)d_out;

  // keep the fixed ncu capture window (our 4th launch) on gemm_xw_k
  dummy_k<<<1, 32>>>();
  dummy_k<<<1, 32>>>();
  dummy_k<<<1, 32>>>();
  gemm_xw_k<<<dim3(512, 8), 256>>>(sentence, table, W_ih_f, W_ih_b,
                                   b_ih_f, b_hh_f, b_ih_b, b_hh_b);
  lstm_k<<<128, 256>>>(W_hh_f, W_hh_b, h0, c0);
  feats_k<<<512, 256>>>(W_out, b_out);
  numer_k<<<128, 128>>>(tags, trans);
  denom_k<<<16, 256>>>(trans);
  mean_k<<<1, 128>>>(out);
}

// round 13
// speedup vs baseline: 1.2455x; 1.1056x over previous
#include <cuda_runtime.h>
#include <cuda_bf16.h>
#include <math.h>

#define SS 512
#define BB 128
#define EE 128
#define HH 128
#define KK 32
#define TAG_START 30
#define TAG_END 31

// ----------------------------- device scratch ------------------------------
__device__ float g_xW[(size_t)SS * BB * 1024];   // [s*B+b][d*512 + g*128 + u]
__device__ float g_hs[2][(size_t)SS * BB * HH];  // per-dir h at original time
__device__ float g_feats[(size_t)BB * SS * KK];  // [b][s][k]
__device__ float g_num[BB];
__device__ float g_den[BB];

// ----------------------------- helpers -------------------------------------
__device__ __forceinline__ void fma2(unsigned long long& d, unsigned long long a,
                                     unsigned long long b) {
  asm("fma.rn.f32x2 %0, %1, %2, %0;" : "+l"(d) : "l"(a), "l"(b));
}
__device__ __forceinline__ float plo(unsigned long long v) {
  return __uint_as_float((unsigned)v);
}
__device__ __forceinline__ float phi(unsigned long long v) {
  return __uint_as_float((unsigned)(v >> 32));
}
__device__ __forceinline__ float sigm(float x) {
  return __fdividef(1.f, 1.f + __expf(-x));
}
__device__ __forceinline__ float ftanh(float x) {
  float e = __expf(-2.f * fmaxf(x, -20.f));
  return __fdividef(1.f - e, 1.f + e);
}
__device__ __forceinline__ unsigned to_tf32(float v) {
  unsigned r;
  asm("cvt.rna.tf32.f32 %0, %1;" : "=r"(r) : "f"(v));
  return r;
}
__device__ __forceinline__ void mma_tf32(float d[4], const unsigned a[4],
                                         const unsigned b[2]) {
  asm volatile(
      "mma.sync.aligned.m16n8k8.row.col.f32.tf32.tf32.f32 "
      "{%0,%1,%2,%3}, {%4,%5,%6,%7}, {%8,%9}, {%0,%1,%2,%3};"
      : "+f"(d[0]), "+f"(d[1]), "+f"(d[2]), "+f"(d[3])
      : "r"(a[0]), "r"(a[1]), "r"(a[2]), "r"(a[3]), "r"(b[0]), "r"(b[1]));
}

#define CLUSTER_SYNC()                                              \
  do {                                                              \
    asm volatile("barrier.cluster.arrive.aligned;" ::: "memory");   \
    asm volatile("barrier.cluster.wait.aligned;" ::: "memory");     \
  } while (0)

// ------------------- profiling-window shim (no-op kernel) ------------------
__global__ void dummy_k() {}

// ------------- 1) fused embedding + input GEMM (tf32 tensor cores) ---------
// xW = X @ Wih^T + b.  M = 65536, N = 1024, K = 128.
// Block 64m x 128n, 8 warps as 2m x 4n (warp tile 32m x 32n),
// mma.sync.m16n8k8 tf32 (fallback HMMA on sm_103a). K chunked by 32.
// A staged [k][m] stride 72, B staged [k][n] stride 136: 8*qk bank rotation
// makes both fragment LDS and staging STS conflict-free.
__global__ void __launch_bounds__(256) gemm_xw_k(
    const int* __restrict__ sentence, const float* __restrict__ table,
    const float* __restrict__ Wf, const float* __restrict__ Wb,
    const float* __restrict__ bihf, const float* __restrict__ bhhf,
    const float* __restrict__ bihb, const float* __restrict__ bhhb) {
  __shared__ __align__(16) unsigned Asu[32 * 72];
  __shared__ __align__(16) unsigned Bsu[32 * 136];
  int tid = threadIdx.x;
  int bm = blockIdx.x, bn = blockIdx.y;
  int r0 = bm * 64, n0 = bn * 128;
  int w = tid >> 5, lane = tid & 31;
  int wm = w & 1, wn = w >> 1;        // warp grid 2m x 4n
  int grp = lane >> 2, qk = lane & 3;

  // A loader: row = tid&63, 8 k per thread (t>>6 selects k-octet)
  int arow = tid & 63, akoff = (tid >> 6) * 8;
  int r = r0 + arow;
  int s = r >> 7, b = r & 127;
  const float* asrc = table + (size_t)sentence[b * SS + s] * EE;
  // B loader: row(n) = tid&127, 16 k per thread
  int brow = tid & 127, bkoff = (tid >> 7) * 16;
  int jg = n0 + brow;
  bool fwd = (n0 < 512);
  const float* wsrc = fwd ? Wf + (size_t)jg * EE
                          : Wb + (size_t)(jg - 512) * EE;

  float d[2][4][4];
#pragma unroll
  for (int mt = 0; mt < 2; mt++)
#pragma unroll
    for (int nt = 0; nt < 4; nt++)
#pragma unroll
      for (int i = 0; i < 4; i++) d[mt][nt][i] = 0.f;

  for (int kt = 0; kt < 4; kt++) {
    int kb = kt * 32;
    // stage A (tf32)
#pragma unroll
    for (int q = 0; q < 2; q++) {
      float4 v = *(const float4*)(asrc + kb + akoff + q * 4);
      Asu[(akoff + q * 4 + 0) * 72 + arow] = to_tf32(v.x);
      Asu[(akoff + q * 4 + 1) * 72 + arow] = to_tf32(v.y);
      Asu[(akoff + q * 4 + 2) * 72 + arow] = to_tf32(v.z);
      Asu[(akoff + q * 4 + 3) * 72 + arow] = to_tf32(v.w);
    }
    // stage B (tf32)
#pragma unroll
    for (int q = 0; q < 4; q++) {
      float4 v = *(const float4*)(wsrc + kb + bkoff + q * 4);
      Bsu[(bkoff + q * 4 + 0) * 136 + brow] = to_tf32(v.x);
      Bsu[(bkoff + q * 4 + 1) * 136 + brow] = to_tf32(v.y);
      Bsu[(bkoff + q * 4 + 2) * 136 + brow] = to_tf32(v.z);
      Bsu[(bkoff + q * 4 + 3) * 136 + brow] = to_tf32(v.w);
    }
    __syncthreads();
#pragma unroll
    for (int ks = 0; ks < 4; ks++) {
      int k0 = ks * 8;
      unsigned a[2][4], bfr[4][2];
#pragma unroll
      for (int mt = 0; mt < 2; mt++) {
        int mb = wm * 32 + mt * 16 + grp;
        a[mt][0] = Asu[(k0 + qk) * 72 + mb];
        a[mt][1] = Asu[(k0 + qk) * 72 + mb + 8];
        a[mt][2] = Asu[(k0 + 4 + qk) * 72 + mb];
        a[mt][3] = Asu[(k0 + 4 + qk) * 72 + mb + 8];
      }
#pragma unroll
      for (int nt = 0; nt < 4; nt++) {
        int nb = wn * 32 + nt * 8 + grp;
        bfr[nt][0] = Bsu[(k0 + qk) * 136 + nb];
        bfr[nt][1] = Bsu[(k0 + 4 + qk) * 136 + nb];
      }
#pragma unroll
      for (int mt = 0; mt < 2; mt++)
#pragma unroll
        for (int nt = 0; nt < 4; nt++) mma_tf32(d[mt][nt], a[mt], bfr[nt]);
    }
    __syncthreads();
  }
  // epilogue: add bias, store float2 pairs
#pragma unroll
  for (int nt = 0; nt < 4; nt++) {
    int col = n0 + wn * 32 + nt * 8 + 2 * qk;
    float bx, by;
    if (fwd) {
      bx = bihf[col] + bhhf[col];
      by = bihf[col + 1] + bhhf[col + 1];
    } else {
      bx = bihb[col - 512] + bhhb[col - 512];
      by = bihb[col - 511] + bhhb[col - 511];
    }
#pragma unroll
    for (int mt = 0; mt < 2; mt++) {
      int m_lo = r0 + wm * 32 + mt * 16 + grp;
      float2 lo = make_float2(d[mt][nt][0] + bx, d[mt][nt][1] + by);
      float2 hi = make_float2(d[mt][nt][2] + bx, d[mt][nt][3] + by);
      *(float2*)&g_xW[(size_t)m_lo * 1024 + col] = lo;
      *(float2*)&g_xW[(size_t)(m_lo + 8) * 1024 + col] = hi;
    }
  }
}

// --------------- 2) bidirectional LSTM recurrence (cluster pairs) ----------
// R6 configuration — best measured (895us). 64 clusters of 2 CTAs; cluster =
// (dir, 4-batch tile); CTA = u-half. W_hh register-resident; h exchanged via
// DSMEM store + one 16-arrival phase-parity mbarrier per step.
__global__ void __cluster_dims__(2, 1, 1) __launch_bounds__(256, 1) lstm_k(
    const float* __restrict__ Whhf, const float* __restrict__ Whhb,
    const float* __restrict__ h0, const float* __restrict__ c0) {
  __shared__ __align__(16) float hb[2][4 * 132];  // [parity][b_local*132 + u]
  __shared__ __align__(8) unsigned long long bar;
  int rank = blockIdx.x & 1;
  int cl = blockIdx.x >> 1;
  int d = cl >> 5;
  int b0 = (cl & 31) * 4;
  int tid = threadIdx.x;
  int lane = tid & 31;
  int wid = tid >> 5;
  int ks = lane >> 3;                 // k-slice 0..3
  int ulg = wid * 8 + (lane & 7);     // 0..63
  int u = rank * 64 + ulg;

  const float* Whh = d ? Whhb : Whhf;
  unsigned long long w2[4][16];
#pragma unroll
  for (int g = 0; g < 4; g++) {
    const float* wr = Whh + (size_t)(g * 128 + u) * 128 + ks * 32;
#pragma unroll
    for (int q = 0; q < 8; q++) {
      ulonglong2 v = *(const ulonglong2*)(wr + q * 4);
      w2[g][q * 2] = v.x;
      w2[g][q * 2 + 1] = v.y;
    }
  }
  for (int i = tid; i < 512; i += 256) {
    int j = i >> 7, uu = i & 127;
    hb[0][j * 132 + uu] = h0[(d * BB + b0 + j) * HH + uu];
  }
  float c = c0[(d * BB + b0 + ks) * HH + u];

  unsigned hb_u32, bar_u32;
  asm("{ .reg .u64 t; cvta.to.shared.u64 t, %1; cvt.u32.u64 %0, t; }"
      : "=r"(hb_u32) : "l"(&hb[0][0]));
  asm("{ .reg .u64 t; cvta.to.shared.u64 t, %1; cvt.u32.u64 %0, t; }"
      : "=r"(bar_u32) : "l"(&bar));
  unsigned peer_base, peer_bar;
  asm("mapa.shared::cluster.u32 %0, %1, %2;"
      : "=r"(peer_base) : "r"(hb_u32), "r"(rank ^ 1));
  asm("mapa.shared::cluster.u32 %0, %1, %2;"
      : "=r"(peer_bar) : "r"(bar_u32), "r"(rank ^ 1));

  if (tid == 0) {
    asm volatile("mbarrier.init.shared.b64 [%0], 16;" :: "r"(bar_u32)
                 : "memory");
  }
  __syncthreads();
  CLUSTER_SYNC();  // mbarrier init visible cluster-wide before any arrive

  for (int t = 0; t < SS; t++) {
    const float* cur = hb[t & 1];
    int np = (t + 1) & 1;
    int tx = d ? (SS - 1 - t) : t;
    float xwv[4];
    const float* xwb =
        g_xW + ((size_t)tx * BB + b0) * 1024 + d * 512 + ks * 128 + u;
#pragma unroll
    for (int j = 0; j < 4; j++) xwv[j] = __ldcg(xwb + j * 1024);

    unsigned long long acc2[4][4];
#pragma unroll
    for (int j = 0; j < 4; j++)
#pragma unroll
      for (int g = 0; g < 4; g++) acc2[j][g] = 0ull;

#pragma unroll
    for (int q = 0; q < 8; q++) {
      int k = ks * 32 + q * 4;
      ulonglong2 hv[4];
#pragma unroll
      for (int j = 0; j < 4; j++)
        hv[j] = *(const ulonglong2*)&cur[j * 132 + k];
#pragma unroll
      for (int j = 0; j < 4; j++)
#pragma unroll
        for (int g = 0; g < 4; g++) {
          fma2(acc2[j][g], hv[j].x, w2[g][q * 2]);
          fma2(acc2[j][g], hv[j].y, w2[g][q * 2 + 1]);
        }
    }
    float acc[4][4];
#pragma unroll
    for (int j = 0; j < 4; j++)
#pragma unroll
      for (int g = 0; g < 4; g++) {
        float v = plo(acc2[j][g]) + phi(acc2[j][g]);
        if (g == ks) v += xwv[j];
        v += __shfl_xor_sync(0xffffffffu, v, 8);
        v += __shfl_xor_sync(0xffffffffu, v, 16);
        acc[j][g] = v;
      }
    float gate[4];
#pragma unroll
    for (int g = 0; g < 4; g++) {
      float a01 = (ks & 1) ? acc[1][g] : acc[0][g];
      float a23 = (ks & 1) ? acc[3][g] : acc[2][g];
      gate[g] = (ks & 2) ? a23 : a01;
    }
    float si = sigm(gate[0]);
    float sf = sigm(gate[1]);
    float tg = ftanh(gate[2]);
    float so = sigm(gate[3]);
    c = sf * c + si * tg;
    float h = so * ftanh(c);
    hb[np][ks * 132 + u] = h;
    unsigned pa = peer_base + (unsigned)(np * 528 + ks * 132 + u) * 4u;
    asm volatile("st.shared::cluster.f32 [%0], %1;" :: "r"(pa), "f"(h));
    g_hs[d][((size_t)tx * BB + b0 + ks) * HH + u] = h;

    __syncwarp();
    if (lane == 0) {
      asm volatile("mbarrier.arrive.release.cta.shared::cta.b64 _, [%0];"
                   :: "r"(bar_u32) : "memory");
      asm volatile(
          "mbarrier.arrive.release.cluster.shared::cluster.b64 _, [%0];"
          :: "r"(peer_bar) : "memory");
    }
    {
      unsigned parity = (unsigned)(t & 1);
      asm volatile(
          "{\n\t"
          ".reg .pred P;\n\t"
          "WL_%=:\n\t"
          "mbarrier.try_wait.parity.acquire.cluster.shared::cta.b64 P, [%0], %1, 0x989680;\n\t"
          "@P bra.uni WD_%=;\n\t"
          "bra.uni WL_%=;\n\t"
          "WD_%=:\n\t"
          "}"
          :: "r"(bar_u32), "r"(parity) : "memory");
    }
  }
}

// -------------- 3) feats = concat(hf,hb) @ Wout^T + bout -------------------
__global__ void __launch_bounds__(256) feats_k(const float* __restrict__ Wout,
                                               const float* __restrict__ bout) {
  __shared__ __align__(16) float Wsh[32 * 260];
  __shared__ float bsh[32];
  int s = blockIdx.x;
  int tid = threadIdx.x;
  for (int i = tid; i < 2048; i += 256) {
    int k = i >> 6, m4 = i & 63;
    float4 v = ((const float4*)Wout)[i];
    *(float4*)&Wsh[k * 260 + m4 * 4] = v;
  }
  if (tid < 32) bsh[tid] = bout[tid];
  __syncthreads();
  int k = tid & 31, b0 = tid >> 5;
  for (int bb = 0; bb < 16; bb++) {
    int b = b0 + bb * 8;
    const float4* hf = (const float4*)&g_hs[0][((size_t)s * BB + b) * HH];
    const float4* hb2 = (const float4*)&g_hs[1][((size_t)s * BB + b) * HH];
    float acc = bsh[k];
#pragma unroll 8
    for (int m4 = 0; m4 < 32; m4++) {
      float4 hv = hf[m4];
      float4 wv = *(const float4*)&Wsh[k * 260 + m4 * 4];
      acc += hv.x * wv.x + hv.y * wv.y + hv.z * wv.z + hv.w * wv.w;
    }
#pragma unroll 8
    for (int m4 = 0; m4 < 32; m4++) {
      float4 hv = hb2[m4];
      float4 wv = *(const float4*)&Wsh[k * 260 + 128 + m4 * 4];
      acc += hv.x * wv.x + hv.y * wv.y + hv.z * wv.z + hv.w * wv.w;
    }
    g_feats[((size_t)b * SS + s) * KK + k] = acc;
  }
}

// ----------------------------- 4) CRF numerator ----------------------------
__global__ void __launch_bounds__(128) numer_k(const int* __restrict__ tags,
                                               const float* __restrict__ T) {
  __shared__ float red[128];
  int b = blockIdx.x;
  int tid = threadIdx.x;
  float sum = 0.f;
  for (int s = tid; s < SS; s += 128) {
    int cur = tags[b * SS + s];
    int prev = (s == 0) ? TAG_START : tags[b * SS + s - 1];
    sum += T[prev * KK + cur] + g_feats[((size_t)b * SS + s) * KK + cur];
  }
  red[tid] = sum;
  __syncthreads();
  for (int off = 64; off > 0; off >>= 1) {
    if (tid < off) red[tid] += red[tid + off];
    __syncthreads();
  }
  if (tid == 0) g_num[b] = red[0] + T[tags[b * SS + SS - 1] * KK + TAG_END];
}

// ---------------------------- 5) CRF denominator ---------------------------
// normalized exp-space scan (verified rel_err 7.1e-7).
__global__ void __launch_bounds__(256) denom_k(const float* __restrict__ T) {
  __shared__ float Tsh[32 * 33];
  int tid = threadIdx.x;
  int lane = tid & 31;
  int warp = tid >> 5;
  int b = blockIdx.x * 8 + warp;
  for (int i = tid; i < 1024; i += 256) Tsh[(i >> 5) * 33 + (i & 31)] = T[i];
  __syncthreads();

  const float* Trow = &Tsh[lane * 33];
  float alpha = (lane == TAG_START) ? 0.f : -10000.f;

  {
    float feat = g_feats[(size_t)b * SS * KK + lane];
    float tmp[32];
    float m = -3.0e38f;
#pragma unroll
    for (int p = 0; p < 32; p++) {
      float ap = __shfl_sync(0xffffffffu, alpha, p);
      tmp[p] = ap + Trow[p];
      m = fmaxf(m, tmp[p]);
    }
    float sum = 0.f;
#pragma unroll
    for (int p = 0; p < 32; p++) sum += __expf(tmp[p] - m);
    alpha = __logf(sum) + m + feat;
  }

  float m0 = alpha;
#pragma unroll
  for (int o = 16; o > 0; o >>= 1)
    m0 = fmaxf(m0, __shfl_xor_sync(0xffffffffu, m0, o));
  float a = __expf(alpha - m0);
  float logacc = m0;

  float rTe[32];
#pragma unroll
  for (int p = 0; p < 32; p++) rTe[p] = __expf(Trow[p]);

  float feat_next = g_feats[((size_t)b * SS + 1) * KK + lane];
  for (int s = 1; s < SS; s++) {
    float feat = feat_next;
    if (s + 1 < SS) feat_next = g_feats[((size_t)b * SS + s + 1) * KK + lane];
    float ef = __expf(feat);
    float t0 = 0.f, t1 = 0.f, t2 = 0.f, t3 = 0.f;
#pragma unroll
    for (int p = 0; p < 32; p += 4) {
      t0 = fmaf(__shfl_sync(0xffffffffu, a, p + 0), rTe[p + 0], t0);
      t1 = fmaf(__shfl_sync(0xffffffffu, a, p + 1), rTe[p + 1], t1);
      t2 = fmaf(__shfl_sync(0xffffffffu, a, p + 2), rTe[p + 2], t2);
      t3 = fmaf(__shfl_sync(0xffffffffu, a, p + 3), rTe[p + 3], t3);
    }
    float u = ((t0 + t1) + (t2 + t3)) * ef;
    float S = u;
#pragma unroll
    for (int o = 16; o > 0; o >>= 1) S += __shfl_xor_sync(0xffffffffu, S, o);
    a = __fdividef(u, S);
    logacc += __logf(S);
  }
  float v = a * __expf(Trow[TAG_END]);
#pragma unroll
  for (int o = 16; o > 0; o >>= 1) v += __shfl_xor_sync(0xffffffffu, v, o);
  if (lane == 0) g_den[b] = logacc + __logf(v);
}

// --------------------------------- 6) mean ---------------------------------
__global__ void __launch_bounds__(128) mean_k(float* __restrict__ out) {
  __shared__ float red[128];
  int tid = threadIdx.x;
  red[tid] = g_num[tid] - g_den[tid];
  __syncthreads();
  for (int off = 64; off > 0; off >>= 1) {
    if (tid < off) red[tid] += red[tid + off];
    __syncthreads();
  }
  if (tid == 0) out[0] = red[0] / 128.0f;
}

// ------------------------------- launcher ----------------------------------
extern "C" void kernel_launch(void* const* d_in, const int* in_sizes, int n_in,
                              void* d_out, int out_size) {
  const int*   sentence = (const int*)d_in[0];
  const int*   tags     = (const int*)d_in[1];
  const float* table    = (const float*)d_in[2];
  const float* W_ih_f   = (const float*)d_in[3];
  const float* W_hh_f   = (const float*)d_in[4];
  const float* b_ih_f   = (const float*)d_in[5];
  const float* b_hh_f   = (const float*)d_in[6];
  const float* W_ih_b   = (const float*)d_in[7];
  const float* W_hh_b   = (const float*)d_in[8];
  const float* b_ih_b   = (const float*)d_in[9];
  const float* b_hh_b   = (const float*)d_in[10];
  const float* W_out    = (const float*)d_in[11];
  const float* b_out    = (const float*)d_in[12];
  const float* trans    = (const float*)d_in[13];
  const float* h0       = (const float*)d_in[14];
  const float* c0       = (const float*)d_in[15];
  float* out = (float*)d_out;

  // keep the fixed ncu capture window (our 4th launch) on gemm_xw_k
  dummy_k<<<1, 32>>>();
  dummy_k<<<1, 32>>>();
  dummy_k<<<1, 32>>>();
  gemm_xw_k<<<dim3(1024, 8), 256>>>(sentence, table, W_ih_f, W_ih_b,
                                    b_ih_f, b_hh_f, b_ih_b, b_hh_b);
  lstm_k<<<128, 256>>>(W_hh_f, W_hh_b, h0, c0);
  feats_k<<<512, 256>>>(W_out, b_out);
  numer_k<<<128, 128>>>(tags, trans);
  denom_k<<<16, 256>>>(trans);
  mean_k<<<1, 128>>>(out);
}

// round 14
// speedup vs baseline: 1.2829x; 1.0300x over previous
#include <cuda_runtime.h>
#include <cuda_bf16.h>
#include <math.h>

#define SS 512
#define BB 128
#define EE 128
#define HH 128
#define KK 32
#define TAG_START 30
#define TAG_END 31

// ----------------------------- device scratch ------------------------------
__device__ float g_xW[(size_t)SS * BB * 1024];   // [s*B+b][d*512 + g*128 + u]
__device__ float g_hs[2][(size_t)SS * BB * HH];  // per-dir h at original time
__device__ float g_feats[(size_t)BB * SS * KK];  // [b][s][k]
__device__ float g_num[BB];
__device__ float g_den[BB];

// ----------------------------- helpers -------------------------------------
__device__ __forceinline__ void fma2(unsigned long long& d, unsigned long long a,
                                     unsigned long long b) {
  asm("fma.rn.f32x2 %0, %1, %2, %0;" : "+l"(d) : "l"(a), "l"(b));
}
__device__ __forceinline__ float plo(unsigned long long v) {
  return __uint_as_float((unsigned)v);
}
__device__ __forceinline__ float phi(unsigned long long v) {
  return __uint_as_float((unsigned)(v >> 32));
}
__device__ __forceinline__ float sigm(float x) {
  return __fdividef(1.f, 1.f + __expf(-x));
}
__device__ __forceinline__ float ftanh(float x) {
  float e = __expf(-2.f * fmaxf(x, -20.f));
  return __fdividef(1.f - e, 1.f + e);
}
// pack (x -> low half / even k, y -> high half / odd k) as bf16x2
__device__ __forceinline__ unsigned bf2(float x, float y) {
  unsigned r;
  asm("cvt.rn.bf16x2.f32 %0, %1, %2;" : "=r"(r) : "f"(y), "f"(x));
  return r;
}
__device__ __forceinline__ void mma_bf16(float d[4], const unsigned a[4],
                                         const unsigned b[2]) {
  asm volatile(
      "mma.sync.aligned.m16n8k16.row.col.f32.bf16.bf16.f32 "
      "{%0,%1,%2,%3}, {%4,%5,%6,%7}, {%8,%9}, {%0,%1,%2,%3};"
      : "+f"(d[0]), "+f"(d[1]), "+f"(d[2]), "+f"(d[3])
      : "r"(a[0]), "r"(a[1]), "r"(a[2]), "r"(a[3]), "r"(b[0]), "r"(b[1]));
}

#define CLUSTER_SYNC()                                              \
  do {                                                              \
    asm volatile("barrier.cluster.arrive.aligned;" ::: "memory");   \
    asm volatile("barrier.cluster.wait.aligned;" ::: "memory");     \
  } while (0)

// ------------------- profiling-window shim (no-op kernel) ------------------
__global__ void dummy_k() {}

// ------------- 1) fused embedding + input GEMM (bf16 tensor cores) ---------
// xW = X @ Wih^T + b.  M = 65536, N = 1024, K = 128.
// Block 64m x 128n, 8 warps as 2m x 4n (warp tile 32m x 32n),
// mma.sync.m16n8k16 bf16. K chunked by 32 (= 16 k-pair rows per chunk).
// Operands staged as bf16x2 u32 rows [k2][m]/[k2][n] with strides 72/136
// (8-bank rotation -> conflict-free fragment LDS and staging STS).
// vs R13 tf32: fragment smem bytes per MAC halved (this was the 90% L1tex
// wall), MMA MACs doubled.
__global__ void __launch_bounds__(256) gemm_xw_k(
    const int* __restrict__ sentence, const float* __restrict__ table,
    const float* __restrict__ Wf, const float* __restrict__ Wb,
    const float* __restrict__ bihf, const float* __restrict__ bhhf,
    const float* __restrict__ bihb, const float* __restrict__ bhhb) {
  __shared__ __align__(16) unsigned Asu[16 * 72];
  __shared__ __align__(16) unsigned Bsu[16 * 136];
  int tid = threadIdx.x;
  int bm = blockIdx.x, bn = blockIdx.y;
  int r0 = bm * 64, n0 = bn * 128;
  int w = tid >> 5, lane = tid & 31;
  int wm = w & 1, wn = w >> 1;        // warp grid 2m x 4n
  int grp = lane >> 2, qk = lane & 3;

  // A loader: m-row = tid&63, 4 k2 (8 floats) per thread
  int arow = tid & 63, ako2 = (tid >> 6) * 4;
  int r = r0 + arow;
  int s = r >> 7, b = r & 127;
  const float* asrc = table + (size_t)sentence[b * SS + s] * EE;
  // B loader: n-row = tid&127, 8 k2 (16 floats) per thread
  int brow = tid & 127, bko2 = (tid >> 7) * 8;
  int jg = n0 + brow;
  bool fwd = (n0 < 512);
  const float* wsrc = fwd ? Wf + (size_t)jg * EE
                          : Wb + (size_t)(jg - 512) * EE;

  float d[2][4][4];
#pragma unroll
  for (int mt = 0; mt < 2; mt++)
#pragma unroll
    for (int nt = 0; nt < 4; nt++)
#pragma unroll
      for (int i = 0; i < 4; i++) d[mt][nt][i] = 0.f;

  for (int kt = 0; kt < 4; kt++) {
    int kb = kt * 32;
    // stage A (bf16x2 rows)
    {
      const float* p = asrc + kb + ako2 * 2;
      float4 v0 = *(const float4*)(p);
      float4 v1 = *(const float4*)(p + 4);
      Asu[(ako2 + 0) * 72 + arow] = bf2(v0.x, v0.y);
      Asu[(ako2 + 1) * 72 + arow] = bf2(v0.z, v0.w);
      Asu[(ako2 + 2) * 72 + arow] = bf2(v1.x, v1.y);
      Asu[(ako2 + 3) * 72 + arow] = bf2(v1.z, v1.w);
    }
    // stage B (bf16x2 rows)
    {
      const float* p = wsrc + kb + bko2 * 2;
#pragma unroll
      for (int q = 0; q < 4; q++) {
        float4 v = *(const float4*)(p + q * 4);
        Bsu[(bko2 + q * 2 + 0) * 136 + brow] = bf2(v.x, v.y);
        Bsu[(bko2 + q * 2 + 1) * 136 + brow] = bf2(v.z, v.w);
      }
    }
    __syncthreads();
#pragma unroll
    for (int ks = 0; ks < 2; ks++) {      // two k16 sub-steps per 32-k chunk
      int k2b = ks * 8;
      unsigned a[2][4], bfr[4][2];
#pragma unroll
      for (int mt = 0; mt < 2; mt++) {
        int mb = wm * 32 + mt * 16 + grp;
        a[mt][0] = Asu[(k2b + qk) * 72 + mb];
        a[mt][1] = Asu[(k2b + qk) * 72 + mb + 8];
        a[mt][2] = Asu[(k2b + 4 + qk) * 72 + mb];
        a[mt][3] = Asu[(k2b + 4 + qk) * 72 + mb + 8];
      }
#pragma unroll
      for (int nt = 0; nt < 4; nt++) {
        int nb = wn * 32 + nt * 8 + grp;
        bfr[nt][0] = Bsu[(k2b + qk) * 136 + nb];
        bfr[nt][1] = Bsu[(k2b + 4 + qk) * 136 + nb];
      }
#pragma unroll
      for (int mt = 0; mt < 2; mt++)
#pragma unroll
        for (int nt = 0; nt < 4; nt++) mma_bf16(d[mt][nt], a[mt], bfr[nt]);
    }
    __syncthreads();
  }
  // epilogue: add bias, store float2 pairs
#pragma unroll
  for (int nt = 0; nt < 4; nt++) {
    int col = n0 + wn * 32 + nt * 8 + 2 * qk;
    float bx, by;
    if (fwd) {
      bx = bihf[col] + bhhf[col];
      by = bihf[col + 1] + bhhf[col + 1];
    } else {
      bx = bihb[col - 512] + bhhb[col - 512];
      by = bihb[col - 511] + bhhb[col - 511];
    }
#pragma unroll
    for (int mt = 0; mt < 2; mt++) {
      int m_lo = r0 + wm * 32 + mt * 16 + grp;
      float2 lo = make_float2(d[mt][nt][0] + bx, d[mt][nt][1] + by);
      float2 hi = make_float2(d[mt][nt][2] + bx, d[mt][nt][3] + by);
      *(float2*)&g_xW[(size_t)m_lo * 1024 + col] = lo;
      *(float2*)&g_xW[(size_t)(m_lo + 8) * 1024 + col] = hi;
    }
  }
}

// --------------- 2) bidirectional LSTM recurrence (cluster pairs) ----------
// R6 configuration — best measured (895us). 64 clusters of 2 CTAs; cluster =
// (dir, 4-batch tile); CTA = u-half. W_hh register-resident; h exchanged via
// DSMEM store + one 16-arrival phase-parity mbarrier per step.
__global__ void __cluster_dims__(2, 1, 1) __launch_bounds__(256, 1) lstm_k(
    const float* __restrict__ Whhf, const float* __restrict__ Whhb,
    const float* __restrict__ h0, const float* __restrict__ c0) {
  __shared__ __align__(16) float hb[2][4 * 132];  // [parity][b_local*132 + u]
  __shared__ __align__(8) unsigned long long bar;
  int rank = blockIdx.x & 1;
  int cl = blockIdx.x >> 1;
  int d = cl >> 5;
  int b0 = (cl & 31) * 4;
  int tid = threadIdx.x;
  int lane = tid & 31;
  int wid = tid >> 5;
  int ks = lane >> 3;                 // k-slice 0..3
  int ulg = wid * 8 + (lane & 7);     // 0..63
  int u = rank * 64 + ulg;

  const float* Whh = d ? Whhb : Whhf;
  unsigned long long w2[4][16];
#pragma unroll
  for (int g = 0; g < 4; g++) {
    const float* wr = Whh + (size_t)(g * 128 + u) * 128 + ks * 32;
#pragma unroll
    for (int q = 0; q < 8; q++) {
      ulonglong2 v = *(const ulonglong2*)(wr + q * 4);
      w2[g][q * 2] = v.x;
      w2[g][q * 2 + 1] = v.y;
    }
  }
  for (int i = tid; i < 512; i += 256) {
    int j = i >> 7, uu = i & 127;
    hb[0][j * 132 + uu] = h0[(d * BB + b0 + j) * HH + uu];
  }
  float c = c0[(d * BB + b0 + ks) * HH + u];

  unsigned hb_u32, bar_u32;
  asm("{ .reg .u64 t; cvta.to.shared.u64 t, %1; cvt.u32.u64 %0, t; }"
      : "=r"(hb_u32) : "l"(&hb[0][0]));
  asm("{ .reg .u64 t; cvta.to.shared.u64 t, %1; cvt.u32.u64 %0, t; }"
      : "=r"(bar_u32) : "l"(&bar));
  unsigned peer_base, peer_bar;
  asm("mapa.shared::cluster.u32 %0, %1, %2;"
      : "=r"(peer_base) : "r"(hb_u32), "r"(rank ^ 1));
  asm("mapa.shared::cluster.u32 %0, %1, %2;"
      : "=r"(peer_bar) : "r"(bar_u32), "r"(rank ^ 1));

  if (tid == 0) {
    asm volatile("mbarrier.init.shared.b64 [%0], 16;" :: "r"(bar_u32)
                 : "memory");
  }
  __syncthreads();
  CLUSTER_SYNC();  // mbarrier init visible cluster-wide before any arrive

  for (int t = 0; t < SS; t++) {
    const float* cur = hb[t & 1];
    int np = (t + 1) & 1;
    int tx = d ? (SS - 1 - t) : t;
    float xwv[4];
    const float* xwb =
        g_xW + ((size_t)tx * BB + b0) * 1024 + d * 512 + ks * 128 + u;
#pragma unroll
    for (int j = 0; j < 4; j++) xwv[j] = __ldcg(xwb + j * 1024);

    unsigned long long acc2[4][4];
#pragma unroll
    for (int j = 0; j < 4; j++)
#pragma unroll
      for (int g = 0; g < 4; g++) acc2[j][g] = 0ull;

#pragma unroll
    for (int q = 0; q < 8; q++) {
      int k = ks * 32 + q * 4;
      ulonglong2 hv[4];
#pragma unroll
      for (int j = 0; j < 4; j++)
        hv[j] = *(const ulonglong2*)&cur[j * 132 + k];
#pragma unroll
      for (int j = 0; j < 4; j++)
#pragma unroll
        for (int g = 0; g < 4; g++) {
          fma2(acc2[j][g], hv[j].x, w2[g][q * 2]);
          fma2(acc2[j][g], hv[j].y, w2[g][q * 2 + 1]);
        }
    }
    float acc[4][4];
#pragma unroll
    for (int j = 0; j < 4; j++)
#pragma unroll
      for (int g = 0; g < 4; g++) {
        float v = plo(acc2[j][g]) + phi(acc2[j][g]);
        if (g == ks) v += xwv[j];
        v += __shfl_xor_sync(0xffffffffu, v, 8);
        v += __shfl_xor_sync(0xffffffffu, v, 16);
        acc[j][g] = v;
      }
    float gate[4];
#pragma unroll
    for (int g = 0; g < 4; g++) {
      float a01 = (ks & 1) ? acc[1][g] : acc[0][g];
      float a23 = (ks & 1) ? acc[3][g] : acc[2][g];
      gate[g] = (ks & 2) ? a23 : a01;
    }
    float si = sigm(gate[0]);
    float sf = sigm(gate[1]);
    float tg = ftanh(gate[2]);
    float so = sigm(gate[3]);
    c = sf * c + si * tg;
    float h = so * ftanh(c);
    hb[np][ks * 132 + u] = h;
    unsigned pa = peer_base + (unsigned)(np * 528 + ks * 132 + u) * 4u;
    asm volatile("st.shared::cluster.f32 [%0], %1;" :: "r"(pa), "f"(h));
    g_hs[d][((size_t)tx * BB + b0 + ks) * HH + u] = h;

    __syncwarp();
    if (lane == 0) {
      asm volatile("mbarrier.arrive.release.cta.shared::cta.b64 _, [%0];"
                   :: "r"(bar_u32) : "memory");
      asm volatile(
          "mbarrier.arrive.release.cluster.shared::cluster.b64 _, [%0];"
          :: "r"(peer_bar) : "memory");
    }
    {
      unsigned parity = (unsigned)(t & 1);
      asm volatile(
          "{\n\t"
          ".reg .pred P;\n\t"
          "WL_%=:\n\t"
          "mbarrier.try_wait.parity.acquire.cluster.shared::cta.b64 P, [%0], %1, 0x989680;\n\t"
          "@P bra.uni WD_%=;\n\t"
          "bra.uni WL_%=;\n\t"
          "WD_%=:\n\t"
          "}"
          :: "r"(bar_u32), "r"(parity) : "memory");
    }
  }
}

// -------------- 3) feats = concat(hf,hb) @ Wout^T + bout -------------------
__global__ void __launch_bounds__(256) feats_k(const float* __restrict__ Wout,
                                               const float* __restrict__ bout) {
  __shared__ __align__(16) float Wsh[32 * 260];
  __shared__ float bsh[32];
  int s = blockIdx.x;
  int tid = threadIdx.x;
  for (int i = tid; i < 2048; i += 256) {
    int k = i >> 6, m4 = i & 63;
    float4 v = ((const float4*)Wout)[i];
    *(float4*)&Wsh[k * 260 + m4 * 4] = v;
  }
  if (tid < 32) bsh[tid] = bout[tid];
  __syncthreads();
  int k = tid & 31, b0 = tid >> 5;
  for (int bb = 0; bb < 16; bb++) {
    int b = b0 + bb * 8;
    const float4* hf = (const float4*)&g_hs[0][((size_t)s * BB + b) * HH];
    const float4* hb2 = (const float4*)&g_hs[1][((size_t)s * BB + b) * HH];
    float acc = bsh[k];
#pragma unroll 8
    for (int m4 = 0; m4 < 32; m4++) {
      float4 hv = hf[m4];
      float4 wv = *(const float4*)&Wsh[k * 260 + m4 * 4];
      acc += hv.x * wv.x + hv.y * wv.y + hv.z * wv.z + hv.w * wv.w;
    }
#pragma unroll 8
    for (int m4 = 0; m4 < 32; m4++) {
      float4 hv = hb2[m4];
      float4 wv = *(const float4*)&Wsh[k * 260 + 128 + m4 * 4];
      acc += hv.x * wv.x + hv.y * wv.y + hv.z * wv.z + hv.w * wv.w;
    }
    g_feats[((size_t)b * SS + s) * KK + k] = acc;
  }
}

// ----------------------------- 4) CRF numerator ----------------------------
__global__ void __launch_bounds__(128) numer_k(const int* __restrict__ tags,
                                               const float* __restrict__ T) {
  __shared__ float red[128];
  int b = blockIdx.x;
  int tid = threadIdx.x;
  float sum = 0.f;
  for (int s = tid; s < SS; s += 128) {
    int cur = tags[b * SS + s];
    int prev = (s == 0) ? TAG_START : tags[b * SS + s - 1];
    sum += T[prev * KK + cur] + g_feats[((size_t)b * SS + s) * KK + cur];
  }
  red[tid] = sum;
  __syncthreads();
  for (int off = 64; off > 0; off >>= 1) {
    if (tid < off) red[tid] += red[tid + off];
    __syncthreads();
  }
  if (tid == 0) g_num[b] = red[0] + T[tags[b * SS + SS - 1] * KK + TAG_END];
}

// ---------------------------- 5) CRF denominator ---------------------------
// normalized exp-space scan (verified rel_err 7.1e-7).
__global__ void __launch_bounds__(256) denom_k(const float* __restrict__ T) {
  __shared__ float Tsh[32 * 33];
  int tid = threadIdx.x;
  int lane = tid & 31;
  int warp = tid >> 5;
  int b = blockIdx.x * 8 + warp;
  for (int i = tid; i < 1024; i += 256) Tsh[(i >> 5) * 33 + (i & 31)] = T[i];
  __syncthreads();

  const float* Trow = &Tsh[lane * 33];
  float alpha = (lane == TAG_START) ? 0.f : -10000.f;

  {
    float feat = g_feats[(size_t)b * SS * KK + lane];
    float tmp[32];
    float m = -3.0e38f;
#pragma unroll
    for (int p = 0; p < 32; p++) {
      float ap = __shfl_sync(0xffffffffu, alpha, p);
      tmp[p] = ap + Trow[p];
      m = fmaxf(m, tmp[p]);
    }
    float sum = 0.f;
#pragma unroll
    for (int p = 0; p < 32; p++) sum += __expf(tmp[p] - m);
    alpha = __logf(sum) + m + feat;
  }

  float m0 = alpha;
#pragma unroll
  for (int o = 16; o > 0; o >>= 1)
    m0 = fmaxf(m0, __shfl_xor_sync(0xffffffffu, m0, o));
  float a = __expf(alpha - m0);
  float logacc = m0;

  float rTe[32];
#pragma unroll
  for (int p = 0; p < 32; p++) rTe[p] = __expf(Trow[p]);

  float feat_next = g_feats[((size_t)b * SS + 1) * KK + lane];
  for (int s = 1; s < SS; s++) {
    float feat = feat_next;
    if (s + 1 < SS) feat_next = g_feats[((size_t)b * SS + s + 1) * KK + lane];
    float ef = __expf(feat);
    float t0 = 0.f, t1 = 0.f, t2 = 0.f, t3 = 0.f;
#pragma unroll
    for (int p = 0; p < 32; p += 4) {
      t0 = fmaf(__shfl_sync(0xffffffffu, a, p + 0), rTe[p + 0], t0);
      t1 = fmaf(__shfl_sync(0xffffffffu, a, p + 1), rTe[p + 1], t1);
      t2 = fmaf(__shfl_sync(0xffffffffu, a, p + 2), rTe[p + 2], t2);
      t3 = fmaf(__shfl_sync(0xffffffffu, a, p + 3), rTe[p + 3], t3);
    }
    float u = ((t0 + t1) + (t2 + t3)) * ef;
    float S = u;
#pragma unroll
    for (int o = 16; o > 0; o >>= 1) S += __shfl_xor_sync(0xffffffffu, S, o);
    a = __fdividef(u, S);
    logacc += __logf(S);
  }
  float v = a * __expf(Trow[TAG_END]);
#pragma unroll
  for (int o = 16; o > 0; o >>= 1) v += __shfl_xor_sync(0xffffffffu, v, o);
  if (lane == 0) g_den[b] = logacc + __logf(v);
}

// --------------------------------- 6) mean ---------------------------------
__global__ void __launch_bounds__(128) mean_k(float* __restrict__ out) {
  __shared__ float red[128];
  int tid = threadIdx.x;
  red[tid] = g_num[tid] - g_den[tid];
  __syncthreads();
  for (int off = 64; off > 0; off >>= 1) {
    if (tid < off) red[tid] += red[tid + off];
    __syncthreads();
  }
  if (tid == 0) out[0] = red[0] / 128.0f;
}

// ------------------------------- launcher ----------------------------------
extern "C" void kernel_launch(void* const* d_in, const int* in_sizes, int n_in,
                              void* d_out, int out_size) {
  const int*   sentence = (const int*)d_in[0];
  const int*   tags     = (const int*)d_in[1];
  const float* table    = (const float*)d_in[2];
  const float* W_ih_f   = (const float*)d_in[3];
  const float* W_hh_f   = (const float*)d_in[4];
  const float* b_ih_f   = (const float*)d_in[5];
  const float* b_hh_f   = (const float*)d_in[6];
  const float* W_ih_b   = (const float*)d_in[7];
  const float* W_hh_b   = (const float*)d_in[8];
  const float* b_ih_b   = (const float*)d_in[9];
  const float* b_hh_b   = (const float*)d_in[10];
  const float* W_out    = (const float*)d_in[11];
  const float* b_out    = (const float*)d_in[12];
  const float* trans    = (const float*)d_in[13];
  const float* h0       = (const float*)d_in[14];
  const float* c0       = (const float*)d_in[15];
  float* out = (float*)d_out;

  // keep the fixed ncu capture window (our 4th launch) on gemm_xw_k
  dummy_k<<<1, 32>>>();
  dummy_k<<<1, 32>>>();
  dummy_k<<<1, 32>>>();
  gemm_xw_k<<<dim3(1024, 8), 256>>>(sentence, table, W_ih_f, W_ih_b,
                                    b_ih_f, b_hh_f, b_ih_b, b_hh_b);
  lstm_k<<<128, 256>>>(W_hh_f, W_hh_b, h0, c0);
  feats_k<<<512, 256>>>(W_out, b_out);
  numer_k<<<128, 128>>>(tags, trans);
  denom_k<<<16, 256>>>(trans);
  mean_k<<<1, 128>>>(out);
}

// round 15
// speedup vs baseline: 1.2996x; 1.0130x over previous
#include <cuda_runtime.h>
#include <cuda_bf16.h>
#include <math.h>

#define SS 512
#define BB 128
#define EE 128
#define HH 128
#define KK 32
#define TAG_START 30
#define TAG_END 31

// ----------------------------- device scratch ------------------------------
__device__ float g_xW[(size_t)SS * BB * 1024];   // [s*B+b][d*512 + g*128 + u]
__device__ float g_hs[2][(size_t)SS * BB * HH];  // per-dir h at original time
__device__ float g_feats[(size_t)BB * SS * KK];  // [b][s][k]
__device__ float g_num[BB];
__device__ float g_den[BB];

// ----------------------------- helpers -------------------------------------
__device__ __forceinline__ void fma2(unsigned long long& d, unsigned long long a,
                                     unsigned long long b) {
  asm("fma.rn.f32x2 %0, %1, %2, %0;" : "+l"(d) : "l"(a), "l"(b));
}
__device__ __forceinline__ float plo(unsigned long long v) {
  return __uint_as_float((unsigned)v);
}
__device__ __forceinline__ float phi(unsigned long long v) {
  return __uint_as_float((unsigned)(v >> 32));
}
__device__ __forceinline__ float sigm(float x) {
  return __fdividef(1.f, 1.f + __expf(-x));
}
__device__ __forceinline__ float ftanh(float x) {
  float e = __expf(-2.f * fmaxf(x, -20.f));
  return __fdividef(1.f - e, 1.f + e);
}
// pack (x -> low half / even k, y -> high half / odd k) as bf16x2
__device__ __forceinline__ unsigned bf2(float x, float y) {
  unsigned r;
  asm("cvt.rn.bf16x2.f32 %0, %1, %2;" : "=r"(r) : "f"(y), "f"(x));
  return r;
}
__device__ __forceinline__ void mma_bf16(float d[4], const unsigned a[4],
                                         const unsigned b[2]) {
  asm volatile(
      "mma.sync.aligned.m16n8k16.row.col.f32.bf16.bf16.f32 "
      "{%0,%1,%2,%3}, {%4,%5,%6,%7}, {%8,%9}, {%0,%1,%2,%3};"
      : "+f"(d[0]), "+f"(d[1]), "+f"(d[2]), "+f"(d[3])
      : "r"(a[0]), "r"(a[1]), "r"(a[2]), "r"(a[3]), "r"(b[0]), "r"(b[1]));
}

#define CLUSTER_SYNC()                                              \
  do {                                                              \
    asm volatile("barrier.cluster.arrive.aligned;" ::: "memory");   \
    asm volatile("barrier.cluster.wait.aligned;" ::: "memory");     \
  } while (0)

// ------------------- profiling-window shim (no-op kernel) ------------------
__global__ void dummy_k() {}

// ------------- 1) fused embedding + input GEMM (bf16 tensor cores) ---------
// xW = X @ Wih^T + b.  M = 65536, N = 1024, K = 128.
// Block 256m x 128n, 8 warps as 4m x 2n (warp tile 64m x 64n) — halves
// fragment smem bytes per MAC vs the 32x32 warp tile (R14: L1tex 90.6%).
// mma.sync.m16n8k16 bf16, K chunked by 32 (16 k-pair rows).
// Operands staged as bf16x2 u32 rows [k2][m] stride 264 / [k2][n] stride 136
// (8-bank rotation -> conflict-free fragment LDS and staging STS).
__global__ void __launch_bounds__(256) gemm_xw_k(
    const int* __restrict__ sentence, const float* __restrict__ table,
    const float* __restrict__ Wf, const float* __restrict__ Wb,
    const float* __restrict__ bihf, const float* __restrict__ bhhf,
    const float* __restrict__ bihb, const float* __restrict__ bhhb) {
  __shared__ __align__(16) unsigned Asu[16 * 264];
  __shared__ __align__(16) unsigned Bsu[16 * 136];
  int tid = threadIdx.x;
  int bm = blockIdx.x, bn = blockIdx.y;
  int r0 = bm * 256, n0 = bn * 128;
  int w = tid >> 5, lane = tid & 31;
  int wm = w >> 1, wn = w & 1;        // warp grid 4m x 2n
  int grp = lane >> 2, qk = lane & 3;

  // A loader: one m-row per thread, 32 floats (16 k2) per chunk
  int arow = tid;
  int r = r0 + arow;
  int s = r >> 7, b = r & 127;
  const float* asrc = table + (size_t)sentence[b * SS + s] * EE;
  // B loader: n-row = tid&127, 16 floats (8 k2) per chunk
  int brow = tid & 127, bko2 = (tid >> 7) * 8;
  int jg = n0 + brow;
  bool fwd = (n0 < 512);
  const float* wsrc = fwd ? Wf + (size_t)jg * EE
                          : Wb + (size_t)(jg - 512) * EE;

  float d[4][8][4];
#pragma unroll
  for (int mt = 0; mt < 4; mt++)
#pragma unroll
    for (int nt = 0; nt < 8; nt++)
#pragma unroll
      for (int i = 0; i < 4; i++) d[mt][nt][i] = 0.f;

  for (int kt = 0; kt < 4; kt++) {
    int kb = kt * 32;
    // stage A (bf16x2 rows, full 16 k2 per row)
#pragma unroll
    for (int q = 0; q < 8; q++) {
      float2 v = *(const float2*)(asrc + kb + q * 4);
      float2 v2 = *(const float2*)(asrc + kb + q * 4 + 2);
      Asu[(q * 2 + 0) * 264 + arow] = bf2(v.x, v.y);
      Asu[(q * 2 + 1) * 264 + arow] = bf2(v2.x, v2.y);
    }
    // stage B (bf16x2 rows)
    {
      const float* p = wsrc + kb + bko2 * 2;
#pragma unroll
      for (int q = 0; q < 4; q++) {
        float4 v = *(const float4*)(p + q * 4);
        Bsu[(bko2 + q * 2 + 0) * 136 + brow] = bf2(v.x, v.y);
        Bsu[(bko2 + q * 2 + 1) * 136 + brow] = bf2(v.z, v.w);
      }
    }
    __syncthreads();
#pragma unroll
    for (int ks = 0; ks < 2; ks++) {      // two k16 sub-steps per 32-k chunk
      int k2b = ks * 8;
      unsigned a[4][4], bfr[8][2];
#pragma unroll
      for (int mt = 0; mt < 4; mt++) {
        int mb = wm * 64 + mt * 16 + grp;
        a[mt][0] = Asu[(k2b + qk) * 264 + mb];
        a[mt][1] = Asu[(k2b + qk) * 264 + mb + 8];
        a[mt][2] = Asu[(k2b + 4 + qk) * 264 + mb];
        a[mt][3] = Asu[(k2b + 4 + qk) * 264 + mb + 8];
      }
#pragma unroll
      for (int nt = 0; nt < 8; nt++) {
        int nb = wn * 64 + nt * 8 + grp;
        bfr[nt][0] = Bsu[(k2b + qk) * 136 + nb];
        bfr[nt][1] = Bsu[(k2b + 4 + qk) * 136 + nb];
      }
#pragma unroll
      for (int mt = 0; mt < 4; mt++)
#pragma unroll
        for (int nt = 0; nt < 8; nt++) mma_bf16(d[mt][nt], a[mt], bfr[nt]);
    }
    __syncthreads();
  }
  // epilogue: add bias, store float2 pairs
#pragma unroll
  for (int nt = 0; nt < 8; nt++) {
    int col = n0 + wn * 64 + nt * 8 + 2 * qk;
    float bx, by;
    if (fwd) {
      bx = bihf[col] + bhhf[col];
      by = bihf[col + 1] + bhhf[col + 1];
    } else {
      bx = bihb[col - 512] + bhhb[col - 512];
      by = bihb[col - 511] + bhhb[col - 511];
    }
#pragma unroll
    for (int mt = 0; mt < 4; mt++) {
      int m_lo = r0 + wm * 64 + mt * 16 + grp;
      float2 lo = make_float2(d[mt][nt][0] + bx, d[mt][nt][1] + by);
      float2 hi = make_float2(d[mt][nt][2] + bx, d[mt][nt][3] + by);
      *(float2*)&g_xW[(size_t)m_lo * 1024 + col] = lo;
      *(float2*)&g_xW[(size_t)(m_lo + 8) * 1024 + col] = hi;
    }
  }
}

// --------------- 2) bidirectional LSTM recurrence (cluster pairs) ----------
// R6 configuration — best measured (895us). 64 clusters of 2 CTAs; cluster =
// (dir, 4-batch tile); CTA = u-half. W_hh register-resident; h exchanged via
// DSMEM store + one 16-arrival phase-parity mbarrier per step.
__global__ void __cluster_dims__(2, 1, 1) __launch_bounds__(256, 1) lstm_k(
    const float* __restrict__ Whhf, const float* __restrict__ Whhb,
    const float* __restrict__ h0, const float* __restrict__ c0) {
  __shared__ __align__(16) float hb[2][4 * 132];  // [parity][b_local*132 + u]
  __shared__ __align__(8) unsigned long long bar;
  int rank = blockIdx.x & 1;
  int cl = blockIdx.x >> 1;
  int d = cl >> 5;
  int b0 = (cl & 31) * 4;
  int tid = threadIdx.x;
  int lane = tid & 31;
  int wid = tid >> 5;
  int ks = lane >> 3;                 // k-slice 0..3
  int ulg = wid * 8 + (lane & 7);     // 0..63
  int u = rank * 64 + ulg;

  const float* Whh = d ? Whhb : Whhf;
  unsigned long long w2[4][16];
#pragma unroll
  for (int g = 0; g < 4; g++) {
    const float* wr = Whh + (size_t)(g * 128 + u) * 128 + ks * 32;
#pragma unroll
    for (int q = 0; q < 8; q++) {
      ulonglong2 v = *(const ulonglong2*)(wr + q * 4);
      w2[g][q * 2] = v.x;
      w2[g][q * 2 + 1] = v.y;
    }
  }
  for (int i = tid; i < 512; i += 256) {
    int j = i >> 7, uu = i & 127;
    hb[0][j * 132 + uu] = h0[(d * BB + b0 + j) * HH + uu];
  }
  float c = c0[(d * BB + b0 + ks) * HH + u];

  unsigned hb_u32, bar_u32;
  asm("{ .reg .u64 t; cvta.to.shared.u64 t, %1; cvt.u32.u64 %0, t; }"
      : "=r"(hb_u32) : "l"(&hb[0][0]));
  asm("{ .reg .u64 t; cvta.to.shared.u64 t, %1; cvt.u32.u64 %0, t; }"
      : "=r"(bar_u32) : "l"(&bar));
  unsigned peer_base, peer_bar;
  asm("mapa.shared::cluster.u32 %0, %1, %2;"
      : "=r"(peer_base) : "r"(hb_u32), "r"(rank ^ 1));
  asm("mapa.shared::cluster.u32 %0, %1, %2;"
      : "=r"(peer_bar) : "r"(bar_u32), "r"(rank ^ 1));

  if (tid == 0) {
    asm volatile("mbarrier.init.shared.b64 [%0], 16;" :: "r"(bar_u32)
                 : "memory");
  }
  __syncthreads();
  CLUSTER_SYNC();  // mbarrier init visible cluster-wide before any arrive

  for (int t = 0; t < SS; t++) {
    const float* cur = hb[t & 1];
    int np = (t + 1) & 1;
    int tx = d ? (SS - 1 - t) : t;
    float xwv[4];
    const float* xwb =
        g_xW + ((size_t)tx * BB + b0) * 1024 + d * 512 + ks * 128 + u;
#pragma unroll
    for (int j = 0; j < 4; j++) xwv[j] = __ldcg(xwb + j * 1024);

    unsigned long long acc2[4][4];
#pragma unroll
    for (int j = 0; j < 4; j++)
#pragma unroll
      for (int g = 0; g < 4; g++) acc2[j][g] = 0ull;

#pragma unroll
    for (int q = 0; q < 8; q++) {
      int k = ks * 32 + q * 4;
      ulonglong2 hv[4];
#pragma unroll
      for (int j = 0; j < 4; j++)
        hv[j] = *(const ulonglong2*)&cur[j * 132 + k];
#pragma unroll
      for (int j = 0; j < 4; j++)
#pragma unroll
        for (int g = 0; g < 4; g++) {
          fma2(acc2[j][g], hv[j].x, w2[g][q * 2]);
          fma2(acc2[j][g], hv[j].y, w2[g][q * 2 + 1]);
        }
    }
    float acc[4][4];
#pragma unroll
    for (int j = 0; j < 4; j++)
#pragma unroll
      for (int g = 0; g < 4; g++) {
        float v = plo(acc2[j][g]) + phi(acc2[j][g]);
        if (g == ks) v += xwv[j];
        v += __shfl_xor_sync(0xffffffffu, v, 8);
        v += __shfl_xor_sync(0xffffffffu, v, 16);
        acc[j][g] = v;
      }
    float gate[4];
#pragma unroll
    for (int g = 0; g < 4; g++) {
      float a01 = (ks & 1) ? acc[1][g] : acc[0][g];
      float a23 = (ks & 1) ? acc[3][g] : acc[2][g];
      gate[g] = (ks & 2) ? a23 : a01;
    }
    float si = sigm(gate[0]);
    float sf = sigm(gate[1]);
    float tg = ftanh(gate[2]);
    float so = sigm(gate[3]);
    c = sf * c + si * tg;
    float h = so * ftanh(c);
    hb[np][ks * 132 + u] = h;
    unsigned pa = peer_base + (unsigned)(np * 528 + ks * 132 + u) * 4u;
    asm volatile("st.shared::cluster.f32 [%0], %1;" :: "r"(pa), "f"(h));
    g_hs[d][((size_t)tx * BB + b0 + ks) * HH + u] = h;

    __syncwarp();
    if (lane == 0) {
      asm volatile("mbarrier.arrive.release.cta.shared::cta.b64 _, [%0];"
                   :: "r"(bar_u32) : "memory");
      asm volatile(
          "mbarrier.arrive.release.cluster.shared::cluster.b64 _, [%0];"
          :: "r"(peer_bar) : "memory");
    }
    {
      unsigned parity = (unsigned)(t & 1);
      asm volatile(
          "{\n\t"
          ".reg .pred P;\n\t"
          "WL_%=:\n\t"
          "mbarrier.try_wait.parity.acquire.cluster.shared::cta.b64 P, [%0], %1, 0x989680;\n\t"
          "@P bra.uni WD_%=;\n\t"
          "bra.uni WL_%=;\n\t"
          "WD_%=:\n\t"
          "}"
          :: "r"(bar_u32), "r"(parity) : "memory");
    }
  }
}

// -------------- 3) feats = concat(hf,hb) @ Wout^T + bout -------------------
__global__ void __launch_bounds__(256) feats_k(const float* __restrict__ Wout,
                                               const float* __restrict__ bout) {
  __shared__ __align__(16) float Wsh[32 * 260];
  __shared__ float bsh[32];
  int s = blockIdx.x;
  int tid = threadIdx.x;
  for (int i = tid; i < 2048; i += 256) {
    int k = i >> 6, m4 = i & 63;
    float4 v = ((const float4*)Wout)[i];
    *(float4*)&Wsh[k * 260 + m4 * 4] = v;
  }
  if (tid < 32) bsh[tid] = bout[tid];
  __syncthreads();
  int k = tid & 31, b0 = tid >> 5;
  for (int bb = 0; bb < 16; bb++) {
    int b = b0 + bb * 8;
    const float4* hf = (const float4*)&g_hs[0][((size_t)s * BB + b) * HH];
    const float4* hb2 = (const float4*)&g_hs[1][((size_t)s * BB + b) * HH];
    float acc = bsh[k];
#pragma unroll 8
    for (int m4 = 0; m4 < 32; m4++) {
      float4 hv = hf[m4];
      float4 wv = *(const float4*)&Wsh[k * 260 + m4 * 4];
      acc += hv.x * wv.x + hv.y * wv.y + hv.z * wv.z + hv.w * wv.w;
    }
#pragma unroll 8
    for (int m4 = 0; m4 < 32; m4++) {
      float4 hv = hb2[m4];
      float4 wv = *(const float4*)&Wsh[k * 260 + 128 + m4 * 4];
      acc += hv.x * wv.x + hv.y * wv.y + hv.z * wv.z + hv.w * wv.w;
    }
    g_feats[((size_t)b * SS + s) * KK + k] = acc;
  }
}

// ----------------------------- 4) CRF numerator ----------------------------
__global__ void __launch_bounds__(128) numer_k(const int* __restrict__ tags,
                                               const float* __restrict__ T) {
  __shared__ float red[128];
  int b = blockIdx.x;
  int tid = threadIdx.x;
  float sum = 0.f;
  for (int s = tid; s < SS; s += 128) {
    int cur = tags[b * SS + s];
    int prev = (s == 0) ? TAG_START : tags[b * SS + s - 1];
    sum += T[prev * KK + cur] + g_feats[((size_t)b * SS + s) * KK + cur];
  }
  red[tid] = sum;
  __syncthreads();
  for (int off = 64; off > 0; off >>= 1) {
    if (tid < off) red[tid] += red[tid + off];
    __syncthreads();
  }
  if (tid == 0) g_num[b] = red[0] + T[tags[b * SS + SS - 1] * KK + TAG_END];
}

// ---------------------------- 5) CRF denominator ---------------------------
// normalized exp-space scan (verified rel_err ~8e-7).
__global__ void __launch_bounds__(256) denom_k(const float* __restrict__ T) {
  __shared__ float Tsh[32 * 33];
  int tid = threadIdx.x;
  int lane = tid & 31;
  int warp = tid >> 5;
  int b = blockIdx.x * 8 + warp;
  for (int i = tid; i < 1024; i += 256) Tsh[(i >> 5) * 33 + (i & 31)] = T[i];
  __syncthreads();

  const float* Trow = &Tsh[lane * 33];
  float alpha = (lane == TAG_START) ? 0.f : -10000.f;

  {
    float feat = g_feats[(size_t)b * SS * KK + lane];
    float tmp[32];
    float m = -3.0e38f;
#pragma unroll
    for (int p = 0; p < 32; p++) {
      float ap = __shfl_sync(0xffffffffu, alpha, p);
      tmp[p] = ap + Trow[p];
      m = fmaxf(m, tmp[p]);
    }
    float sum = 0.f;
#pragma unroll
    for (int p = 0; p < 32; p++) sum += __expf(tmp[p] - m);
    alpha = __logf(sum) + m + feat;
  }

  float m0 = alpha;
#pragma unroll
  for (int o = 16; o > 0; o >>= 1)
    m0 = fmaxf(m0, __shfl_xor_sync(0xffffffffu, m0, o));
  float a = __expf(alpha - m0);
  float logacc = m0;

  float rTe[32];
#pragma unroll
  for (int p = 0; p < 32; p++) rTe[p] = __expf(Trow[p]);

  float feat_next = g_feats[((size_t)b * SS + 1) * KK + lane];
  for (int s = 1; s < SS; s++) {
    float feat = feat_next;
    if (s + 1 < SS) feat_next = g_feats[((size_t)b * SS + s + 1) * KK + lane];
    float ef = __expf(feat);
    float t0 = 0.f, t1 = 0.f, t2 = 0.f, t3 = 0.f;
#pragma unroll
    for (int p = 0; p < 32; p += 4) {
      t0 = fmaf(__shfl_sync(0xffffffffu, a, p + 0), rTe[p + 0], t0);
      t1 = fmaf(__shfl_sync(0xffffffffu, a, p + 1), rTe[p + 1], t1);
      t2 = fmaf(__shfl_sync(0xffffffffu, a, p + 2), rTe[p + 2], t2);
      t3 = fmaf(__shfl_sync(0xffffffffu, a, p + 3), rTe[p + 3], t3);
    }
    float u = ((t0 + t1) + (t2 + t3)) * ef;
    float S = u;
#pragma unroll
    for (int o = 16; o > 0; o >>= 1) S += __shfl_xor_sync(0xffffffffu, S, o);
    a = __fdividef(u, S);
    logacc += __logf(S);
  }
  float v = a * __expf(Trow[TAG_END]);
#pragma unroll
  for (int o = 16; o > 0; o >>= 1) v += __shfl_xor_sync(0xffffffffu, v, o);
  if (lane == 0) g_den[b] = logacc + __logf(v);
}

// --------------------------------- 6) mean ---------------------------------
__global__ void __launch_bounds__(128) mean_k(float* __restrict__ out) {
  __shared__ float red[128];
  int tid = threadIdx.x;
  red[tid] = g_num[tid] - g_den[tid];
  __syncthreads();
  for (int off = 64; off > 0; off >>= 1) {
    if (tid < off) red[tid] += red[tid + off];
    __syncthreads();
  }
  if (tid == 0) out[0] = red[0] / 128.0f;
}

// ------------------------------- launcher ----------------------------------
extern "C" void kernel_launch(void* const* d_in, const int* in_sizes, int n_in,
                              void* d_out, int out_size) {
  const int*   sentence = (const int*)d_in[0];
  const int*   tags     = (const int*)d_in[1];
  const float* table    = (const float*)d_in[2];
  const float* W_ih_f   = (const float*)d_in[3];
  const float* W_hh_f   = (const float*)d_in[4];
  const float* b_ih_f   = (const float*)d_in[5];
  const float* b_hh_f   = (const float*)d_in[6];
  const float* W_ih_b   = (const float*)d_in[7];
  const float* W_hh_b   = (const float*)d_in[8];
  const float* b_ih_b   = (const float*)d_in[9];
  const float* b_hh_b   = (const float*)d_in[10];
  const float* W_out    = (const float*)d_in[11];
  const float* b_out    = (const float*)d_in[12];
  const float* trans    = (const float*)d_in[13];
  const float* h0       = (const float*)d_in[14];
  const float* c0       = (const float*)d_in[15];
  float* out = (float*)d_out;

  // ncu window = 4th launch -> feats_k this round (hunt the unaccounted time)
  dummy_k<<<1, 32>>>();
  gemm_xw_k<<<dim3(256, 8), 256>>>(sentence, table, W_ih_f, W_ih_b,
                                   b_ih_f, b_hh_f, b_ih_b, b_hh_b);
  lstm_k<<<128, 256>>>(W_hh_f, W_hh_b, h0, c0);
  feats_k<<<512, 256>>>(W_out, b_out);
  numer_k<<<128, 128>>>(tags, trans);
  denom_k<<<16, 256>>>(trans);
  mean_k<<<1, 128>>>(out);
}

// round 16
// speedup vs baseline: 1.4278x; 1.0986x over previous
#include <cuda_runtime.h>
#include <cuda_bf16.h>
#include <math.h>

#define SS 512
#define BB 128
#define EE 128
#define HH 128
#define KK 32
#define TAG_START 30
#define TAG_END 31

// ----------------------------- device scratch ------------------------------
__device__ float g_xW[(size_t)SS * BB * 1024];     // [s*B+b][d*512+g*128+u]
__device__ __nv_bfloat16 g_hs_bf[2][(size_t)SS * BB * HH];  // h in bf16
__device__ float g_feats[(size_t)BB * SS * KK];    // [b][s][k]
__device__ float g_num[BB];
__device__ float g_den[BB];

// ----------------------------- helpers -------------------------------------
__device__ __forceinline__ void fma2(unsigned long long& d, unsigned long long a,
                                     unsigned long long b) {
  asm("fma.rn.f32x2 %0, %1, %2, %0;" : "+l"(d) : "l"(a), "l"(b));
}
__device__ __forceinline__ float plo(unsigned long long v) {
  return __uint_as_float((unsigned)v);
}
__device__ __forceinline__ float phi(unsigned long long v) {
  return __uint_as_float((unsigned)(v >> 32));
}
__device__ __forceinline__ float sigm(float x) {
  return __fdividef(1.f, 1.f + __expf(-x));
}
__device__ __forceinline__ float ftanh(float x) {
  float e = __expf(-2.f * fmaxf(x, -20.f));
  return __fdividef(1.f - e, 1.f + e);
}
// pack (x -> low half / even k, y -> high half / odd k) as bf16x2
__device__ __forceinline__ unsigned bf2(float x, float y) {
  unsigned r;
  asm("cvt.rn.bf16x2.f32 %0, %1, %2;" : "=r"(r) : "f"(y), "f"(x));
  return r;
}
__device__ __forceinline__ void mma_bf16(float d[4], const unsigned a[4],
                                         const unsigned b[2]) {
  asm volatile(
      "mma.sync.aligned.m16n8k16.row.col.f32.bf16.bf16.f32 "
      "{%0,%1,%2,%3}, {%4,%5,%6,%7}, {%8,%9}, {%0,%1,%2,%3};"
      : "+f"(d[0]), "+f"(d[1]), "+f"(d[2]), "+f"(d[3])
      : "r"(a[0]), "r"(a[1]), "r"(a[2]), "r"(a[3]), "r"(b[0]), "r"(b[1]));
}

#define CLUSTER_SYNC()                                              \
  do {                                                              \
    asm volatile("barrier.cluster.arrive.aligned;" ::: "memory");   \
    asm volatile("barrier.cluster.wait.aligned;" ::: "memory");     \
  } while (0)

// ------------------- profiling-window shim (no-op kernel) ------------------
__global__ void dummy_k() {}

// ------------- 1) fused embedding + input GEMM (bf16 tensor cores) ---------
// xW = X @ Wih^T + b.  M = 65536, N = 1024, K = 128.
// Block 256m x 128n, 8 warps as 4m x 2n (warp tile 64m x 64n).
__global__ void __launch_bounds__(256) gemm_xw_k(
    const int* __restrict__ sentence, const float* __restrict__ table,
    const float* __restrict__ Wf, const float* __restrict__ Wb,
    const float* __restrict__ bihf, const float* __restrict__ bhhf,
    const float* __restrict__ bihb, const float* __restrict__ bhhb) {
  __shared__ __align__(16) unsigned Asu[16 * 264];
  __shared__ __align__(16) unsigned Bsu[16 * 136];
  int tid = threadIdx.x;
  int bm = blockIdx.x, bn = blockIdx.y;
  int r0 = bm * 256, n0 = bn * 128;
  int w = tid >> 5, lane = tid & 31;
  int wm = w >> 1, wn = w & 1;        // warp grid 4m x 2n
  int grp = lane >> 2, qk = lane & 3;

  int arow = tid;
  int r = r0 + arow;
  int s = r >> 7, b = r & 127;
  const float* asrc = table + (size_t)sentence[b * SS + s] * EE;
  int brow = tid & 127, bko2 = (tid >> 7) * 8;
  int jg = n0 + brow;
  bool fwd = (n0 < 512);
  const float* wsrc = fwd ? Wf + (size_t)jg * EE
                          : Wb + (size_t)(jg - 512) * EE;

  float d[4][8][4];
#pragma unroll
  for (int mt = 0; mt < 4; mt++)
#pragma unroll
    for (int nt = 0; nt < 8; nt++)
#pragma unroll
      for (int i = 0; i < 4; i++) d[mt][nt][i] = 0.f;

  for (int kt = 0; kt < 4; kt++) {
    int kb = kt * 32;
#pragma unroll
    for (int q = 0; q < 8; q++) {
      float2 v = *(const float2*)(asrc + kb + q * 4);
      float2 v2 = *(const float2*)(asrc + kb + q * 4 + 2);
      Asu[(q * 2 + 0) * 264 + arow] = bf2(v.x, v.y);
      Asu[(q * 2 + 1) * 264 + arow] = bf2(v2.x, v2.y);
    }
    {
      const float* p = wsrc + kb + bko2 * 2;
#pragma unroll
      for (int q = 0; q < 4; q++) {
        float4 v = *(const float4*)(p + q * 4);
        Bsu[(bko2 + q * 2 + 0) * 136 + brow] = bf2(v.x, v.y);
        Bsu[(bko2 + q * 2 + 1) * 136 + brow] = bf2(v.z, v.w);
      }
    }
    __syncthreads();
#pragma unroll
    for (int ks = 0; ks < 2; ks++) {
      int k2b = ks * 8;
      unsigned a[4][4], bfr[8][2];
#pragma unroll
      for (int mt = 0; mt < 4; mt++) {
        int mb = wm * 64 + mt * 16 + grp;
        a[mt][0] = Asu[(k2b + qk) * 264 + mb];
        a[mt][1] = Asu[(k2b + qk) * 264 + mb + 8];
        a[mt][2] = Asu[(k2b + 4 + qk) * 264 + mb];
        a[mt][3] = Asu[(k2b + 4 + qk) * 264 + mb + 8];
      }
#pragma unroll
      for (int nt = 0; nt < 8; nt++) {
        int nb = wn * 64 + nt * 8 + grp;
        bfr[nt][0] = Bsu[(k2b + qk) * 136 + nb];
        bfr[nt][1] = Bsu[(k2b + 4 + qk) * 136 + nb];
      }
#pragma unroll
      for (int mt = 0; mt < 4; mt++)
#pragma unroll
        for (int nt = 0; nt < 8; nt++) mma_bf16(d[mt][nt], a[mt], bfr[nt]);
    }
    __syncthreads();
  }
#pragma unroll
  for (int nt = 0; nt < 8; nt++) {
    int col = n0 + wn * 64 + nt * 8 + 2 * qk;
    float bx, by;
    if (fwd) {
      bx = bihf[col] + bhhf[col];
      by = bihf[col + 1] + bhhf[col + 1];
    } else {
      bx = bihb[col - 512] + bhhb[col - 512];
      by = bihb[col - 511] + bhhb[col - 511];
    }
#pragma unroll
    for (int mt = 0; mt < 4; mt++) {
      int m_lo = r0 + wm * 64 + mt * 16 + grp;
      float2 lo = make_float2(d[mt][nt][0] + bx, d[mt][nt][1] + by);
      float2 hi = make_float2(d[mt][nt][2] + bx, d[mt][nt][3] + by);
      *(float2*)&g_xW[(size_t)m_lo * 1024 + col] = lo;
      *(float2*)&g_xW[(size_t)(m_lo + 8) * 1024 + col] = hi;
    }
  }
}

// --------------- 2) bidirectional LSTM recurrence (cluster pairs) ----------
// R6 configuration — best measured. h history now written in bf16.
__global__ void __cluster_dims__(2, 1, 1) __launch_bounds__(256, 1) lstm_k(
    const float* __restrict__ Whhf, const float* __restrict__ Whhb,
    const float* __restrict__ h0, const float* __restrict__ c0) {
  __shared__ __align__(16) float hb[2][4 * 132];  // [parity][b_local*132 + u]
  __shared__ __align__(8) unsigned long long bar;
  int rank = blockIdx.x & 1;
  int cl = blockIdx.x >> 1;
  int d = cl >> 5;
  int b0 = (cl & 31) * 4;
  int tid = threadIdx.x;
  int lane = tid & 31;
  int wid = tid >> 5;
  int ks = lane >> 3;                 // k-slice 0..3
  int ulg = wid * 8 + (lane & 7);     // 0..63
  int u = rank * 64 + ulg;

  const float* Whh = d ? Whhb : Whhf;
  unsigned long long w2[4][16];
#pragma unroll
  for (int g = 0; g < 4; g++) {
    const float* wr = Whh + (size_t)(g * 128 + u) * 128 + ks * 32;
#pragma unroll
    for (int q = 0; q < 8; q++) {
      ulonglong2 v = *(const ulonglong2*)(wr + q * 4);
      w2[g][q * 2] = v.x;
      w2[g][q * 2 + 1] = v.y;
    }
  }
  for (int i = tid; i < 512; i += 256) {
    int j = i >> 7, uu = i & 127;
    hb[0][j * 132 + uu] = h0[(d * BB + b0 + j) * HH + uu];
  }
  float c = c0[(d * BB + b0 + ks) * HH + u];

  unsigned hb_u32, bar_u32;
  asm("{ .reg .u64 t; cvta.to.shared.u64 t, %1; cvt.u32.u64 %0, t; }"
      : "=r"(hb_u32) : "l"(&hb[0][0]));
  asm("{ .reg .u64 t; cvta.to.shared.u64 t, %1; cvt.u32.u64 %0, t; }"
      : "=r"(bar_u32) : "l"(&bar));
  unsigned peer_base, peer_bar;
  asm("mapa.shared::cluster.u32 %0, %1, %2;"
      : "=r"(peer_base) : "r"(hb_u32), "r"(rank ^ 1));
  asm("mapa.shared::cluster.u32 %0, %1, %2;"
      : "=r"(peer_bar) : "r"(bar_u32), "r"(rank ^ 1));

  if (tid == 0) {
    asm volatile("mbarrier.init.shared.b64 [%0], 16;" :: "r"(bar_u32)
                 : "memory");
  }
  __syncthreads();
  CLUSTER_SYNC();

  for (int t = 0; t < SS; t++) {
    const float* cur = hb[t & 1];
    int np = (t + 1) & 1;
    int tx = d ? (SS - 1 - t) : t;
    float xwv[4];
    const float* xwb =
        g_xW + ((size_t)tx * BB + b0) * 1024 + d * 512 + ks * 128 + u;
#pragma unroll
    for (int j = 0; j < 4; j++) xwv[j] = __ldcg(xwb + j * 1024);

    unsigned long long acc2[4][4];
#pragma unroll
    for (int j = 0; j < 4; j++)
#pragma unroll
      for (int g = 0; g < 4; g++) acc2[j][g] = 0ull;

#pragma unroll
    for (int q = 0; q < 8; q++) {
      int k = ks * 32 + q * 4;
      ulonglong2 hv[4];
#pragma unroll
      for (int j = 0; j < 4; j++)
        hv[j] = *(const ulonglong2*)&cur[j * 132 + k];
#pragma unroll
      for (int j = 0; j < 4; j++)
#pragma unroll
        for (int g = 0; g < 4; g++) {
          fma2(acc2[j][g], hv[j].x, w2[g][q * 2]);
          fma2(acc2[j][g], hv[j].y, w2[g][q * 2 + 1]);
        }
    }
    float acc[4][4];
#pragma unroll
    for (int j = 0; j < 4; j++)
#pragma unroll
      for (int g = 0; g < 4; g++) {
        float v = plo(acc2[j][g]) + phi(acc2[j][g]);
        if (g == ks) v += xwv[j];
        v += __shfl_xor_sync(0xffffffffu, v, 8);
        v += __shfl_xor_sync(0xffffffffu, v, 16);
        acc[j][g] = v;
      }
    float gate[4];
#pragma unroll
    for (int g = 0; g < 4; g++) {
      float a01 = (ks & 1) ? acc[1][g] : acc[0][g];
      float a23 = (ks & 1) ? acc[3][g] : acc[2][g];
      gate[g] = (ks & 2) ? a23 : a01;
    }
    float si = sigm(gate[0]);
    float sf = sigm(gate[1]);
    float tg = ftanh(gate[2]);
    float so = sigm(gate[3]);
    c = sf * c + si * tg;
    float h = so * ftanh(c);
    hb[np][ks * 132 + u] = h;
    unsigned pa = peer_base + (unsigned)(np * 528 + ks * 132 + u) * 4u;
    asm volatile("st.shared::cluster.f32 [%0], %1;" :: "r"(pa), "f"(h));
    g_hs_bf[d][((size_t)tx * BB + b0 + ks) * HH + u] = __float2bfloat16(h);

    __syncwarp();
    if (lane == 0) {
      asm volatile("mbarrier.arrive.release.cta.shared::cta.b64 _, [%0];"
                   :: "r"(bar_u32) : "memory");
      asm volatile(
          "mbarrier.arrive.release.cluster.shared::cluster.b64 _, [%0];"
          :: "r"(peer_bar) : "memory");
    }
    {
      unsigned parity = (unsigned)(t & 1);
      asm volatile(
          "{\n\t"
          ".reg .pred P;\n\t"
          "WL_%=:\n\t"
          "mbarrier.try_wait.parity.acquire.cluster.shared::cta.b64 P, [%0], %1, 0x989680;\n\t"
          "@P bra.uni WD_%=;\n\t"
          "bra.uni WL_%=;\n\t"
          "WD_%=:\n\t"
          "}"
          :: "r"(bar_u32), "r"(parity) : "memory");
    }
  }
}

// -------- 3) feats = concat(hf,hb) @ Wout^T + bout (bf16 tensor cores) -----
// M = 65536 (m = s*B+b), N = 32, K = 256 (k<128: dir0, k>=128: dir1).
// Block 256m x 32n, 8 warps as 8m x 1n (warp tile 32m x 32n, verified
// fragment layout). Wout staged once as bf16x2 [k2=128][n=32] stride 40;
// A chunks [k2=16][m=256] stride 264 loaded from bf16 g_hs_bf (native pairs).
__global__ void __launch_bounds__(256) feats_k(const float* __restrict__ Wout,
                                               const float* __restrict__ bout) {
  __shared__ __align__(16) unsigned Asu[16 * 264];
  __shared__ __align__(16) unsigned Bsu[128 * 40];
  __shared__ float bsh[32];
  int tid = threadIdx.x;
  int m0 = blockIdx.x * 256;
  int w = tid >> 5, lane = tid & 31;
  int grp = lane >> 2, qk = lane & 3;

  // stage B entire: n = tid&31, 16 k2 per thread starting (tid>>5)*16
  {
    int n = tid & 31;
    int ko2 = (tid >> 5) * 16;
    const float* p = Wout + (size_t)n * 256 + ko2 * 2;
#pragma unroll
    for (int q = 0; q < 8; q++) {
      float4 v = *(const float4*)(p + q * 4);
      Bsu[(ko2 + q * 2 + 0) * 40 + n] = bf2(v.x, v.y);
      Bsu[(ko2 + q * 2 + 1) * 40 + n] = bf2(v.z, v.w);
    }
  }
  if (tid < 32) bsh[tid] = bout[tid];

  float d[2][4][4];
#pragma unroll
  for (int mt = 0; mt < 2; mt++)
#pragma unroll
    for (int nt = 0; nt < 4; nt++)
#pragma unroll
      for (int i = 0; i < 4; i++) d[mt][nt][i] = 0.f;

  int m = m0 + tid;  // A loader row
  for (int kt = 0; kt < 8; kt++) {
    int dsel = kt >> 2;
    int u0 = (kt & 3) * 32;
    // A chunk: 32 bf16 = 16 u32 contiguous
    const uint4* src = (const uint4*)(&g_hs_bf[dsel][(size_t)m * HH + u0]);
    __syncthreads();   // protect previous iteration's reads
#pragma unroll
    for (int q = 0; q < 4; q++) {
      uint4 v = src[q];
      Asu[(q * 4 + 0) * 264 + tid] = v.x;
      Asu[(q * 4 + 1) * 264 + tid] = v.y;
      Asu[(q * 4 + 2) * 264 + tid] = v.z;
      Asu[(q * 4 + 3) * 264 + tid] = v.w;
    }
    __syncthreads();
#pragma unroll
    for (int ks = 0; ks < 2; ks++) {
      int k2b = ks * 8;
      int k2g = kt * 16 + k2b;
      unsigned a[2][4], bfr[4][2];
#pragma unroll
      for (int mt = 0; mt < 2; mt++) {
        int mb = w * 32 + mt * 16 + grp;
        a[mt][0] = Asu[(k2b + qk) * 264 + mb];
        a[mt][1] = Asu[(k2b + qk) * 264 + mb + 8];
        a[mt][2] = Asu[(k2b + 4 + qk) * 264 + mb];
        a[mt][3] = Asu[(k2b + 4 + qk) * 264 + mb + 8];
      }
#pragma unroll
      for (int nt = 0; nt < 4; nt++) {
        int nb = nt * 8 + grp;
        bfr[nt][0] = Bsu[(k2g + qk) * 40 + nb];
        bfr[nt][1] = Bsu[(k2g + 4 + qk) * 40 + nb];
      }
#pragma unroll
      for (int mt = 0; mt < 2; mt++)
#pragma unroll
        for (int nt = 0; nt < 4; nt++) mma_bf16(d[mt][nt], a[mt], bfr[nt]);
    }
  }
  // epilogue: scatter to g_feats[b][s][k] (m = s*B+b)
#pragma unroll
  for (int nt = 0; nt < 4; nt++) {
    int col = nt * 8 + 2 * qk;
    float bx = bsh[col], by = bsh[col + 1];
#pragma unroll
    for (int mt = 0; mt < 2; mt++) {
      int m_lo = m0 + w * 32 + mt * 16 + grp;
      int s_lo = m_lo >> 7, b_lo = m_lo & 127;
      int m_hi = m_lo + 8;
      int s_hi = m_hi >> 7, b_hi = m_hi & 127;
      *(float2*)&g_feats[((size_t)b_lo * SS + s_lo) * KK + col] =
          make_float2(d[mt][nt][0] + bx, d[mt][nt][1] + by);
      *(float2*)&g_feats[((size_t)b_hi * SS + s_hi) * KK + col] =
          make_float2(d[mt][nt][2] + bx, d[mt][nt][3] + by);
    }
  }
}

// ----------------------------- 4) CRF numerator ----------------------------
__global__ void __launch_bounds__(128) numer_k(const int* __restrict__ tags,
                                               const float* __restrict__ T) {
  __shared__ float red[128];
  int b = blockIdx.x;
  int tid = threadIdx.x;
  float sum = 0.f;
  for (int s = tid; s < SS; s += 128) {
    int cur = tags[b * SS + s];
    int prev = (s == 0) ? TAG_START : tags[b * SS + s - 1];
    sum += T[prev * KK + cur] + g_feats[((size_t)b * SS + s) * KK + cur];
  }
  red[tid] = sum;
  __syncthreads();
  for (int off = 64; off > 0; off >>= 1) {
    if (tid < off) red[tid] += red[tid + off];
    __syncthreads();
  }
  if (tid == 0) g_num[b] = red[0] + T[tags[b * SS + SS - 1] * KK + TAG_END];
}

// ---------------------------- 5) CRF denominator ---------------------------
// normalized exp-space scan (verified).
__global__ void __launch_bounds__(256) denom_k(const float* __restrict__ T) {
  __shared__ float Tsh[32 * 33];
  int tid = threadIdx.x;
  int lane = tid & 31;
  int warp = tid >> 5;
  int b = blockIdx.x * 8 + warp;
  for (int i = tid; i < 1024; i += 256) Tsh[(i >> 5) * 33 + (i & 31)] = T[i];
  __syncthreads();

  const float* Trow = &Tsh[lane * 33];
  float alpha = (lane == TAG_START) ? 0.f : -10000.f;

  {
    float feat = g_feats[(size_t)b * SS * KK + lane];
    float tmp[32];
    float m = -3.0e38f;
#pragma unroll
    for (int p = 0; p < 32; p++) {
      float ap = __shfl_sync(0xffffffffu, alpha, p);
      tmp[p] = ap + Trow[p];
      m = fmaxf(m, tmp[p]);
    }
    float sum = 0.f;
#pragma unroll
    for (int p = 0; p < 32; p++) sum += __expf(tmp[p] - m);
    alpha = __logf(sum) + m + feat;
  }

  float m0 = alpha;
#pragma unroll
  for (int o = 16; o > 0; o >>= 1)
    m0 = fmaxf(m0, __shfl_xor_sync(0xffffffffu, m0, o));
  float a = __expf(alpha - m0);
  float logacc = m0;

  float rTe[32];
#pragma unroll
  for (int p = 0; p < 32; p++) rTe[p] = __expf(Trow[p]);

  float feat_next = g_feats[((size_t)b * SS + 1) * KK + lane];
  for (int s = 1; s < SS; s++) {
    float feat = feat_next;
    if (s + 1 < SS) feat_next = g_feats[((size_t)b * SS + s + 1) * KK + lane];
    float ef = __expf(feat);
    float t0 = 0.f, t1 = 0.f, t2 = 0.f, t3 = 0.f;
#pragma unroll
    for (int p = 0; p < 32; p += 4) {
      t0 = fmaf(__shfl_sync(0xffffffffu, a, p + 0), rTe[p + 0], t0);
      t1 = fmaf(__shfl_sync(0xffffffffu, a, p + 1), rTe[p + 1], t1);
      t2 = fmaf(__shfl_sync(0xffffffffu, a, p + 2), rTe[p + 2], t2);
      t3 = fmaf(__shfl_sync(0xffffffffu, a, p + 3), rTe[p + 3], t3);
    }
    float u = ((t0 + t1) + (t2 + t3)) * ef;
    float S = u;
#pragma unroll
    for (int o = 16; o > 0; o >>= 1) S += __shfl_xor_sync(0xffffffffu, S, o);
    a = __fdividef(u, S);
    logacc += __logf(S);
  }
  float v = a * __expf(Trow[TAG_END]);
#pragma unroll
  for (int o = 16; o > 0; o >>= 1) v += __shfl_xor_sync(0xffffffffu, v, o);
  if (lane == 0) g_den[b] = logacc + __logf(v);
}

// --------------------------------- 6) mean ---------------------------------
__global__ void __launch_bounds__(128) mean_k(float* __restrict__ out) {
  __shared__ float red[128];
  int tid = threadIdx.x;
  red[tid] = g_num[tid] - g_den[tid];
  __syncthreads();
  for (int off = 64; off > 0; off >>= 1) {
    if (tid < off) red[tid] += red[tid + off];
    __syncthreads();
  }
  if (tid == 0) out[0] = red[0] / 128.0f;
}

// ------------------------------- launcher ----------------------------------
extern "C" void kernel_launch(void* const* d_in, const int* in_sizes, int n_in,
                              void* d_out, int out_size) {
  const int*   sentence = (const int*)d_in[0];
  const int*   tags     = (const int*)d_in[1];
  const float* table    = (const float*)d_in[2];
  const float* W_ih_f   = (const float*)d_in[3];
  const float* W_hh_f   = (const float*)d_in[4];
  const float* b_ih_f   = (const float*)d_in[5];
  const float* b_hh_f   = (const float*)d_in[6];
  const float* W_ih_b   = (const float*)d_in[7];
  const float* W_hh_b   = (const float*)d_in[8];
  const float* b_ih_b   = (const float*)d_in[9];
  const float* b_hh_b   = (const float*)d_in[10];
  const float* W_out    = (const float*)d_in[11];
  const float* b_out    = (const float*)d_in[12];
  const float* trans    = (const float*)d_in[13];
  const float* h0       = (const float*)d_in[14];
  const float* c0       = (const float*)d_in[15];
  float* out = (float*)d_out;

  // ncu window = 4th launch -> new feats_k (verify the GEMM rewrite)
  dummy_k<<<1, 32>>>();
  gemm_xw_k<<<dim3(256, 8), 256>>>(sentence, table, W_ih_f, W_ih_b,
                                   b_ih_f, b_hh_f, b_ih_b, b_hh_b);
  lstm_k<<<128, 256>>>(W_hh_f, W_hh_b, h0, c0);
  feats_k<<<256, 256>>>(W_out, b_out);
  numer_k<<<128, 128>>>(tags, trans);
  denom_k<<<16, 256>>>(trans);
  mean_k<<<1, 128>>>(out);
}

// round 17
// speedup vs baseline: 1.4427x; 1.0105x over previous
#include <cuda_runtime.h>
#include <cuda_bf16.h>
#include <math.h>

#define SS 512
#define BB 128
#define EE 128
#define HH 128
#define KK 32
#define TAG_START 30
#define TAG_END 31

// ----------------------------- device scratch ------------------------------
__device__ float g_xW[(size_t)SS * BB * 1024];     // [s*B+b][d*512+g*128+u]
__device__ unsigned g_X2[(size_t)SS * BB * 64];    // embedded X, bf16x2 rows
__device__ __nv_bfloat16 g_hs_bf[2][(size_t)SS * BB * HH];  // h in bf16
__device__ float g_feats[(size_t)BB * SS * KK];    // [b][s][k]
__device__ float g_num[BB];
__device__ float g_den[BB];

// ----------------------------- helpers -------------------------------------
__device__ __forceinline__ void fma2(unsigned long long& d, unsigned long long a,
                                     unsigned long long b) {
  asm("fma.rn.f32x2 %0, %1, %2, %0;" : "+l"(d) : "l"(a), "l"(b));
}
__device__ __forceinline__ float plo(unsigned long long v) {
  return __uint_as_float((unsigned)v);
}
__device__ __forceinline__ float phi(unsigned long long v) {
  return __uint_as_float((unsigned)(v >> 32));
}
__device__ __forceinline__ float sigm(float x) {
  return __fdividef(1.f, 1.f + __expf(-x));
}
__device__ __forceinline__ float ftanh(float x) {
  float e = __expf(-2.f * fmaxf(x, -20.f));
  return __fdividef(1.f - e, 1.f + e);
}
// pack (x -> low half / even k, y -> high half / odd k) as bf16x2
__device__ __forceinline__ unsigned bf2(float x, float y) {
  unsigned r;
  asm("cvt.rn.bf16x2.f32 %0, %1, %2;" : "=r"(r) : "f"(y), "f"(x));
  return r;
}
__device__ __forceinline__ void mma_bf16(float d[4], const unsigned a[4],
                                         const unsigned b[2]) {
  asm volatile(
      "mma.sync.aligned.m16n8k16.row.col.f32.bf16.bf16.f32 "
      "{%0,%1,%2,%3}, {%4,%5,%6,%7}, {%8,%9}, {%0,%1,%2,%3};"
      : "+f"(d[0]), "+f"(d[1]), "+f"(d[2]), "+f"(d[3])
      : "r"(a[0]), "r"(a[1]), "r"(a[2]), "r"(a[3]), "r"(b[0]), "r"(b[1]));
}

#define CLUSTER_SYNC()                                              \
  do {                                                              \
    asm volatile("barrier.cluster.arrive.aligned;" ::: "memory");   \
    asm volatile("barrier.cluster.wait.aligned;" ::: "memory");     \
  } while (0)

// ------------------- profiling-window shim (no-op kernel) ------------------
__global__ void dummy_k() {}

// ------- 0) embedding gather -> dense bf16 rows (single gather pass) -------
// Removes the 8x-repeated random-row gather from the input GEMM (R14/R16:
// L1tex ~90% there; scattered LDGs touch ~32 lines each).
__global__ void __launch_bounds__(256) embed_bf_k(
    const int* __restrict__ sentence, const float* __restrict__ table) {
  int idx = blockIdx.x * 256 + threadIdx.x;  // 524288 total
  int r = idx >> 3;
  int q = idx & 7;                            // 16-float chunk
  int s = r >> 7, b = r & 127;
  const float* src = table + (size_t)sentence[b * SS + s] * EE + q * 16;
  float4 v0 = *(const float4*)(src);
  float4 v1 = *(const float4*)(src + 4);
  float4 v2 = *(const float4*)(src + 8);
  float4 v3 = *(const float4*)(src + 12);
  uint4 o0 = make_uint4(bf2(v0.x, v0.y), bf2(v0.z, v0.w),
                        bf2(v1.x, v1.y), bf2(v1.z, v1.w));
  uint4 o1 = make_uint4(bf2(v2.x, v2.y), bf2(v2.z, v2.w),
                        bf2(v3.x, v3.y), bf2(v3.z, v3.w));
  uint4* dst = (uint4*)(g_X2 + (size_t)r * 64 + q * 8);
  dst[0] = o0;
  dst[1] = o1;
}

// ------------- 1) input GEMM (bf16 tensor cores, dense A) ------------------
// xW = X @ Wih^T + b.  M = 65536, N = 1024, K = 128.
// Block 256m x 128n, 8 warps as 4m x 2n (warp tile 64m x 64n).
// A read dense from g_X2 (bf16x2, no cvt); B cvt-staged from weights.
__global__ void __launch_bounds__(256) gemm_xw_k(
    const float* __restrict__ Wf, const float* __restrict__ Wb,
    const float* __restrict__ bihf, const float* __restrict__ bhhf,
    const float* __restrict__ bihb, const float* __restrict__ bhhb) {
  __shared__ __align__(16) unsigned Asu[16 * 264];
  __shared__ __align__(16) unsigned Bsu[16 * 136];
  int tid = threadIdx.x;
  int bm = blockIdx.x, bn = blockIdx.y;
  int r0 = bm * 256, n0 = bn * 128;
  int w = tid >> 5, lane = tid & 31;
  int wm = w >> 1, wn = w & 1;        // warp grid 4m x 2n
  int grp = lane >> 2, qk = lane & 3;

  int arow = tid;
  const unsigned* a2src = g_X2 + (size_t)(r0 + arow) * 64;
  int brow = tid & 127, bko2 = (tid >> 7) * 8;
  int jg = n0 + brow;
  bool fwd = (n0 < 512);
  const float* wsrc = fwd ? Wf + (size_t)jg * EE
                          : Wb + (size_t)(jg - 512) * EE;

  float d[4][8][4];
#pragma unroll
  for (int mt = 0; mt < 4; mt++)
#pragma unroll
    for (int nt = 0; nt < 8; nt++)
#pragma unroll
      for (int i = 0; i < 4; i++) d[mt][nt][i] = 0.f;

  for (int kt = 0; kt < 4; kt++) {
    // stage A: dense uint4 loads, 16 u32 per row chunk
    {
      const uint4* p = (const uint4*)(a2src + kt * 16);
      uint4 u0 = p[0], u1 = p[1], u2 = p[2], u3 = p[3];
      Asu[0 * 264 + arow] = u0.x;  Asu[1 * 264 + arow] = u0.y;
      Asu[2 * 264 + arow] = u0.z;  Asu[3 * 264 + arow] = u0.w;
      Asu[4 * 264 + arow] = u1.x;  Asu[5 * 264 + arow] = u1.y;
      Asu[6 * 264 + arow] = u1.z;  Asu[7 * 264 + arow] = u1.w;
      Asu[8 * 264 + arow] = u2.x;  Asu[9 * 264 + arow] = u2.y;
      Asu[10 * 264 + arow] = u2.z; Asu[11 * 264 + arow] = u2.w;
      Asu[12 * 264 + arow] = u3.x; Asu[13 * 264 + arow] = u3.y;
      Asu[14 * 264 + arow] = u3.z; Asu[15 * 264 + arow] = u3.w;
    }
    {
      const float* p = wsrc + kt * 32 + bko2 * 2;
#pragma unroll
      for (int q = 0; q < 4; q++) {
        float4 v = *(const float4*)(p + q * 4);
        Bsu[(bko2 + q * 2 + 0) * 136 + brow] = bf2(v.x, v.y);
        Bsu[(bko2 + q * 2 + 1) * 136 + brow] = bf2(v.z, v.w);
      }
    }
    __syncthreads();
#pragma unroll
    for (int ks = 0; ks < 2; ks++) {
      int k2b = ks * 8;
      unsigned a[4][4], bfr[8][2];
#pragma unroll
      for (int mt = 0; mt < 4; mt++) {
        int mb = wm * 64 + mt * 16 + grp;
        a[mt][0] = Asu[(k2b + qk) * 264 + mb];
        a[mt][1] = Asu[(k2b + qk) * 264 + mb + 8];
        a[mt][2] = Asu[(k2b + 4 + qk) * 264 + mb];
        a[mt][3] = Asu[(k2b + 4 + qk) * 264 + mb + 8];
      }
#pragma unroll
      for (int nt = 0; nt < 8; nt++) {
        int nb = wn * 64 + nt * 8 + grp;
        bfr[nt][0] = Bsu[(k2b + qk) * 136 + nb];
        bfr[nt][1] = Bsu[(k2b + 4 + qk) * 136 + nb];
      }
#pragma unroll
      for (int mt = 0; mt < 4; mt++)
#pragma unroll
        for (int nt = 0; nt < 8; nt++) mma_bf16(d[mt][nt], a[mt], bfr[nt]);
    }
    __syncthreads();
  }
#pragma unroll
  for (int nt = 0; nt < 8; nt++) {
    int col = n0 + wn * 64 + nt * 8 + 2 * qk;
    float bx, by;
    if (fwd) {
      bx = bihf[col] + bhhf[col];
      by = bihf[col + 1] + bhhf[col + 1];
    } else {
      bx = bihb[col - 512] + bhhb[col - 512];
      by = bihb[col - 511] + bhhb[col - 511];
    }
#pragma unroll
    for (int mt = 0; mt < 4; mt++) {
      int m_lo = r0 + wm * 64 + mt * 16 + grp;
      float2 lo = make_float2(d[mt][nt][0] + bx, d[mt][nt][1] + by);
      float2 hi = make_float2(d[mt][nt][2] + bx, d[mt][nt][3] + by);
      *(float2*)&g_xW[(size_t)m_lo * 1024 + col] = lo;
      *(float2*)&g_xW[(size_t)(m_lo + 8) * 1024 + col] = hi;
    }
  }
}

// --------------- 2) bidirectional LSTM recurrence (cluster pairs) ----------
// R6 configuration (best measured) + one-step-ahead xW prefetch: the 4 xW
// loads for step t+1 are issued right after step t's mbarrier arrive, giving
// them a full step (~2500cyc) of cover instead of ~500.
__global__ void __cluster_dims__(2, 1, 1) __launch_bounds__(256, 1) lstm_k(
    const float* __restrict__ Whhf, const float* __restrict__ Whhb,
    const float* __restrict__ h0, const float* __restrict__ c0) {
  __shared__ __align__(16) float hb[2][4 * 132];  // [parity][b_local*132 + u]
  __shared__ __align__(8) unsigned long long bar;
  int rank = blockIdx.x & 1;
  int cl = blockIdx.x >> 1;
  int d = cl >> 5;
  int b0 = (cl & 31) * 4;
  int tid = threadIdx.x;
  int lane = tid & 31;
  int wid = tid >> 5;
  int ks = lane >> 3;                 // k-slice 0..3
  int ulg = wid * 8 + (lane & 7);     // 0..63
  int u = rank * 64 + ulg;

  const float* Whh = d ? Whhb : Whhf;
  unsigned long long w2[4][16];
#pragma unroll
  for (int g = 0; g < 4; g++) {
    const float* wr = Whh + (size_t)(g * 128 + u) * 128 + ks * 32;
#pragma unroll
    for (int q = 0; q < 8; q++) {
      ulonglong2 v = *(const ulonglong2*)(wr + q * 4);
      w2[g][q * 2] = v.x;
      w2[g][q * 2 + 1] = v.y;
    }
  }
  for (int i = tid; i < 512; i += 256) {
    int j = i >> 7, uu = i & 127;
    hb[0][j * 132 + uu] = h0[(d * BB + b0 + j) * HH + uu];
  }
  float c = c0[(d * BB + b0 + ks) * HH + u];

  unsigned hb_u32, bar_u32;
  asm("{ .reg .u64 t; cvta.to.shared.u64 t, %1; cvt.u32.u64 %0, t; }"
      : "=r"(hb_u32) : "l"(&hb[0][0]));
  asm("{ .reg .u64 t; cvta.to.shared.u64 t, %1; cvt.u32.u64 %0, t; }"
      : "=r"(bar_u32) : "l"(&bar));
  unsigned peer_base, peer_bar;
  asm("mapa.shared::cluster.u32 %0, %1, %2;"
      : "=r"(peer_base) : "r"(hb_u32), "r"(rank ^ 1));
  asm("mapa.shared::cluster.u32 %0, %1, %2;"
      : "=r"(peer_bar) : "r"(bar_u32), "r"(rank ^ 1));

  if (tid == 0) {
    asm volatile("mbarrier.init.shared.b64 [%0], 16;" :: "r"(bar_u32)
                 : "memory");
  }
  __syncthreads();
  CLUSTER_SYNC();

  auto xw_addr = [&](int t) -> const float* {
    int txi = d ? (SS - 1 - t) : t;
    return g_xW + ((size_t)txi * BB + b0) * 1024 + d * 512 + ks * 128 + u;
  };
  float xwv[4];
  {
    const float* p = xw_addr(0);
#pragma unroll
    for (int j = 0; j < 4; j++) xwv[j] = __ldcg(p + j * 1024);
  }

  for (int t = 0; t < SS; t++) {
    const float* cur = hb[t & 1];
    int np = (t + 1) & 1;
    int tx = d ? (SS - 1 - t) : t;

    unsigned long long acc2[4][4];
#pragma unroll
    for (int j = 0; j < 4; j++)
#pragma unroll
      for (int g = 0; g < 4; g++) acc2[j][g] = 0ull;

#pragma unroll
    for (int q = 0; q < 8; q++) {
      int k = ks * 32 + q * 4;
      ulonglong2 hv[4];
#pragma unroll
      for (int j = 0; j < 4; j++)
        hv[j] = *(const ulonglong2*)&cur[j * 132 + k];
#pragma unroll
      for (int j = 0; j < 4; j++)
#pragma unroll
        for (int g = 0; g < 4; g++) {
          fma2(acc2[j][g], hv[j].x, w2[g][q * 2]);
          fma2(acc2[j][g], hv[j].y, w2[g][q * 2 + 1]);
        }
    }
    float acc[4][4];
#pragma unroll
    for (int j = 0; j < 4; j++)
#pragma unroll
      for (int g = 0; g < 4; g++) {
        float v = plo(acc2[j][g]) + phi(acc2[j][g]);
        if (g == ks) v += xwv[j];
        v += __shfl_xor_sync(0xffffffffu, v, 8);
        v += __shfl_xor_sync(0xffffffffu, v, 16);
        acc[j][g] = v;
      }
    float gate[4];
#pragma unroll
    for (int g = 0; g < 4; g++) {
      float a01 = (ks & 1) ? acc[1][g] : acc[0][g];
      float a23 = (ks & 1) ? acc[3][g] : acc[2][g];
      gate[g] = (ks & 2) ? a23 : a01;
    }
    float si = sigm(gate[0]);
    float sf = sigm(gate[1]);
    float tg = ftanh(gate[2]);
    float so = sigm(gate[3]);
    c = sf * c + si * tg;
    float h = so * ftanh(c);
    hb[np][ks * 132 + u] = h;
    unsigned pa = peer_base + (unsigned)(np * 528 + ks * 132 + u) * 4u;
    asm volatile("st.shared::cluster.f32 [%0], %1;" :: "r"(pa), "f"(h));
    g_hs_bf[d][((size_t)tx * BB + b0 + ks) * HH + u] = __float2bfloat16(h);

    __syncwarp();
    if (lane == 0) {
      asm volatile("mbarrier.arrive.release.cta.shared::cta.b64 _, [%0];"
                   :: "r"(bar_u32) : "memory");
      asm volatile(
          "mbarrier.arrive.release.cluster.shared::cluster.b64 _, [%0];"
          :: "r"(peer_bar) : "memory");
    }
    // prefetch next step's xW under the barrier wait + next matvec
    {
      int tn = (t + 1 < SS) ? t + 1 : SS - 1;
      const float* p = xw_addr(tn);
#pragma unroll
      for (int j = 0; j < 4; j++) xwv[j] = __ldcg(p + j * 1024);
    }
    {
      unsigned parity = (unsigned)(t & 1);
      asm volatile(
          "{\n\t"
          ".reg .pred P;\n\t"
          "WL_%=:\n\t"
          "mbarrier.try_wait.parity.acquire.cluster.shared::cta.b64 P, [%0], %1, 0x989680;\n\t"
          "@P bra.uni WD_%=;\n\t"
          "bra.uni WL_%=;\n\t"
          "WD_%=:\n\t"
          "}"
          :: "r"(bar_u32), "r"(parity) : "memory");
    }
  }
}

// -------- 3) feats = concat(hf,hb) @ Wout^T + bout (bf16 tensor cores) -----
__global__ void __launch_bounds__(256) feats_k(const float* __restrict__ Wout,
                                               const float* __restrict__ bout) {
  __shared__ __align__(16) unsigned Asu[16 * 264];
  __shared__ __align__(16) unsigned Bsu[128 * 40];
  __shared__ float bsh[32];
  int tid = threadIdx.x;
  int m0 = blockIdx.x * 256;
  int w = tid >> 5, lane = tid & 31;
  int grp = lane >> 2, qk = lane & 3;

  {
    int n = tid & 31;
    int ko2 = (tid >> 5) * 16;
    const float* p = Wout + (size_t)n * 256 + ko2 * 2;
#pragma unroll
    for (int q = 0; q < 8; q++) {
      float4 v = *(const float4*)(p + q * 4);
      Bsu[(ko2 + q * 2 + 0) * 40 + n] = bf2(v.x, v.y);
      Bsu[(ko2 + q * 2 + 1) * 40 + n] = bf2(v.z, v.w);
    }
  }
  if (tid < 32) bsh[tid] = bout[tid];

  float d[2][4][4];
#pragma unroll
  for (int mt = 0; mt < 2; mt++)
#pragma unroll
    for (int nt = 0; nt < 4; nt++)
#pragma unroll
      for (int i = 0; i < 4; i++) d[mt][nt][i] = 0.f;

  int m = m0 + tid;
  for (int kt = 0; kt < 8; kt++) {
    int dsel = kt >> 2;
    int u0 = (kt & 3) * 32;
    const uint4* src = (const uint4*)(&g_hs_bf[dsel][(size_t)m * HH + u0]);
    __syncthreads();
#pragma unroll
    for (int q = 0; q < 4; q++) {
      uint4 v = src[q];
      Asu[(q * 4 + 0) * 264 + tid] = v.x;
      Asu[(q * 4 + 1) * 264 + tid] = v.y;
      Asu[(q * 4 + 2) * 264 + tid] = v.z;
      Asu[(q * 4 + 3) * 264 + tid] = v.w;
    }
    __syncthreads();
#pragma unroll
    for (int ks = 0; ks < 2; ks++) {
      int k2b = ks * 8;
      int k2g = kt * 16 + k2b;
      unsigned a[2][4], bfr[4][2];
#pragma unroll
      for (int mt = 0; mt < 2; mt++) {
        int mb = w * 32 + mt * 16 + grp;
        a[mt][0] = Asu[(k2b + qk) * 264 + mb];
        a[mt][1] = Asu[(k2b + qk) * 264 + mb + 8];
        a[mt][2] = Asu[(k2b + 4 + qk) * 264 + mb];
        a[mt][3] = Asu[(k2b + 4 + qk) * 264 + mb + 8];
      }
#pragma unroll
      for (int nt = 0; nt < 4; nt++) {
        int nb = nt * 8 + grp;
        bfr[nt][0] = Bsu[(k2g + qk) * 40 + nb];
        bfr[nt][1] = Bsu[(k2g + 4 + qk) * 40 + nb];
      }
#pragma unroll
      for (int mt = 0; mt < 2; mt++)
#pragma unroll
        for (int nt = 0; nt < 4; nt++) mma_bf16(d[mt][nt], a[mt], bfr[nt]);
    }
  }
#pragma unroll
  for (int nt = 0; nt < 4; nt++) {
    int col = nt * 8 + 2 * qk;
    float bx = bsh[col], by = bsh[col + 1];
#pragma unroll
    for (int mt = 0; mt < 2; mt++) {
      int m_lo = m0 + w * 32 + mt * 16 + grp;
      int s_lo = m_lo >> 7, b_lo = m_lo & 127;
      int m_hi = m_lo + 8;
      int s_hi = m_hi >> 7, b_hi = m_hi & 127;
      *(float2*)&g_feats[((size_t)b_lo * SS + s_lo) * KK + col] =
          make_float2(d[mt][nt][0] + bx, d[mt][nt][1] + by);
      *(float2*)&g_feats[((size_t)b_hi * SS + s_hi) * KK + col] =
          make_float2(d[mt][nt][2] + bx, d[mt][nt][3] + by);
    }
  }
}

// ----------------------------- 4) CRF numerator ----------------------------
__global__ void __launch_bounds__(128) numer_k(const int* __restrict__ tags,
                                               const float* __restrict__ T) {
  __shared__ float red[128];
  int b = blockIdx.x;
  int tid = threadIdx.x;
  float sum = 0.f;
  for (int s = tid; s < SS; s += 128) {
    int cur = tags[b * SS + s];
    int prev = (s == 0) ? TAG_START : tags[b * SS + s - 1];
    sum += T[prev * KK + cur] + g_feats[((size_t)b * SS + s) * KK + cur];
  }
  red[tid] = sum;
  __syncthreads();
  for (int off = 64; off > 0; off >>= 1) {
    if (tid < off) red[tid] += red[tid + off];
    __syncthreads();
  }
  if (tid == 0) g_num[b] = red[0] + T[tags[b * SS + SS - 1] * KK + TAG_END];
}

// ---------------------------- 5) CRF denominator ---------------------------
__global__ void __launch_bounds__(256) denom_k(const float* __restrict__ T) {
  __shared__ float Tsh[32 * 33];
  int tid = threadIdx.x;
  int lane = tid & 31;
  int warp = tid >> 5;
  int b = blockIdx.x * 8 + warp;
  for (int i = tid; i < 1024; i += 256) Tsh[(i >> 5) * 33 + (i & 31)] = T[i];
  __syncthreads();

  const float* Trow = &Tsh[lane * 33];
  float alpha = (lane == TAG_START) ? 0.f : -10000.f;

  {
    float feat = g_feats[(size_t)b * SS * KK + lane];
    float tmp[32];
    float m = -3.0e38f;
#pragma unroll
    for (int p = 0; p < 32; p++) {
      float ap = __shfl_sync(0xffffffffu, alpha, p);
      tmp[p] = ap + Trow[p];
      m = fmaxf(m, tmp[p]);
    }
    float sum = 0.f;
#pragma unroll
    for (int p = 0; p < 32; p++) sum += __expf(tmp[p] - m);
    alpha = __logf(sum) + m + feat;
  }

  float m0 = alpha;
#pragma unroll
  for (int o = 16; o > 0; o >>= 1)
    m0 = fmaxf(m0, __shfl_xor_sync(0xffffffffu, m0, o));
  float a = __expf(alpha - m0);
  float logacc = m0;

  float rTe[32];
#pragma unroll
  for (int p = 0; p < 32; p++) rTe[p] = __expf(Trow[p]);

  float feat_next = g_feats[((size_t)b * SS + 1) * KK + lane];
  for (int s = 1; s < SS; s++) {
    float feat = feat_next;
    if (s + 1 < SS) feat_next = g_feats[((size_t)b * SS + s + 1) * KK + lane];
    float ef = __expf(feat);
    float t0 = 0.f, t1 = 0.f, t2 = 0.f, t3 = 0.f;
#pragma unroll
    for (int p = 0; p < 32; p += 4) {
      t0 = fmaf(__shfl_sync(0xffffffffu, a, p + 0), rTe[p + 0], t0);
      t1 = fmaf(__shfl_sync(0xffffffffu, a, p + 1), rTe[p + 1], t1);
      t2 = fmaf(__shfl_sync(0xffffffffu, a, p + 2), rTe[p + 2], t2);
      t3 = fmaf(__shfl_sync(0xffffffffu, a, p + 3), rTe[p + 3], t3);
    }
    float u = ((t0 + t1) + (t2 + t3)) * ef;
    float S = u;
#pragma unroll
    for (int o = 16; o > 0; o >>= 1) S += __shfl_xor_sync(0xffffffffu, S, o);
    a = __fdividef(u, S);
    logacc += __logf(S);
  }
  float v = a * __expf(Trow[TAG_END]);
#pragma unroll
  for (int o = 16; o > 0; o >>= 1) v += __shfl_xor_sync(0xffffffffu, v, o);
  if (lane == 0) g_den[b] = logacc + __logf(v);
}

// --------------------------------- 6) mean ---------------------------------
__global__ void __launch_bounds__(128) mean_k(float* __restrict__ out) {
  __shared__ float red[128];
  int tid = threadIdx.x;
  red[tid] = g_num[tid] - g_den[tid];
  __syncthreads();
  for (int off = 64; off > 0; off >>= 1) {
    if (tid < off) red[tid] += red[tid + off];
    __syncthreads();
  }
  if (tid == 0) out[0] = red[0] / 128.0f;
}

// ------------------------------- launcher ----------------------------------
extern "C" void kernel_launch(void* const* d_in, const int* in_sizes, int n_in,
                              void* d_out, int out_size) {
  const int*   sentence = (const int*)d_in[0];
  const int*   tags     = (const int*)d_in[1];
  const float* table    = (const float*)d_in[2];
  const float* W_ih_f   = (const float*)d_in[3];
  const float* W_hh_f   = (const float*)d_in[4];
  const float* b_ih_f   = (const float*)d_in[5];
  const float* b_hh_f   = (const float*)d_in[6];
  const float* W_ih_b   = (const float*)d_in[7];
  const float* W_hh_b   = (const float*)d_in[8];
  const float* b_ih_b   = (const float*)d_in[9];
  const float* b_hh_b   = (const float*)d_in[10];
  const float* W_out    = (const float*)d_in[11];
  const float* b_out    = (const float*)d_in[12];
  const float* trans    = (const float*)d_in[13];
  const float* h0       = (const float*)d_in[14];
  const float* c0       = (const float*)d_in[15];
  float* out = (float*)d_out;

  // ncu window = 4th launch -> gemm_xw_k (verify dense-A theory)
  embed_bf_k<<<2048, 256>>>(sentence, table);
  dummy_k<<<1, 32>>>();
  dummy_k<<<1, 32>>>();
  gemm_xw_k<<<dim3(256, 8), 256>>>(W_ih_f, W_ih_b,
                                   b_ih_f, b_hh_f, b_ih_b, b_hh_b);
  lstm_k<<<128, 256>>>(W_hh_f, W_hh_b, h0, c0);
  feats_k<<<256, 256>>>(W_out, b_out);
  numer_k<<<128, 128>>>(tags, trans);
  denom_k<<<16, 256>>>(trans);
  mean_k<<<1, 128>>>(out);
}